// round 9
// baseline (speedup 1.0000x reference)
#include <cuda_runtime.h>
#include <cuda_bf16.h>
#include <cstdint>

// Problem constants
#define B_  8
#define T_  1024
#define C_  768
#define H_  12
#define HS_ 64
#define M_  8192   // B*T

// ---------------------------------------------------------------------------
// Device-global scratch (no runtime allocation allowed)
// ---------------------------------------------------------------------------
__device__ __nv_bfloat16 g_XH[(size_t)M_*C_], g_XL[(size_t)M_*C_];
__device__ __nv_bfloat16 g_YH[(size_t)M_*C_], g_YL[(size_t)M_*C_];
__device__ __nv_bfloat16 g_WaH[(size_t)3*C_*C_], g_WaL[(size_t)3*C_*C_];
__device__ __nv_bfloat16 g_WpH[(size_t)C_*C_],   g_WpL[(size_t)C_*C_];

// Q/K: [B,H,T,hs] bf16 hi/lo (Q prescaled by 0.125). V: TRANSPOSED [B,H,hs,T].
__device__ __nv_bfloat16 g_Qh[B_*H_*T_*HS_], g_Ql[B_*H_*T_*HS_];
__device__ __nv_bfloat16 g_Kh[B_*H_*T_*HS_], g_Kl[B_*H_*T_*HS_];
__device__ __nv_bfloat16 g_Vh[B_*H_*T_*HS_], g_Vl[B_*H_*T_*HS_];

// ---------------------------------------------------------------------------
// Helpers (portable PTX only — compiles for plain sm_103 target)
// ---------------------------------------------------------------------------
__device__ __forceinline__ uint32_t smem_u32(const void* p){
    return (uint32_t)__cvta_generic_to_shared(p);
}
__device__ __forceinline__ void cpa16(uint32_t d, const void* s){
    asm volatile("cp.async.cg.shared.global [%0], [%1], 16;" :: "r"(d), "l"(s));
}
__device__ __forceinline__ void ldsm4(uint32_t& r0, uint32_t& r1,
                                      uint32_t& r2, uint32_t& r3, uint32_t a){
    asm volatile("ldmatrix.sync.aligned.m8n8.x4.shared.b16 {%0,%1,%2,%3}, [%4];"
                 : "=r"(r0), "=r"(r1), "=r"(r2), "=r"(r3) : "r"(a));
}
__device__ __forceinline__ void mma16816(float acc[4], const uint32_t a[4],
                                         const uint32_t b[2]){
    asm volatile(
        "mma.sync.aligned.m16n8k16.row.col.f32.bf16.bf16.f32 "
        "{%0,%1,%2,%3}, {%4,%5,%6,%7}, {%8,%9}, {%0,%1,%2,%3};"
        : "+f"(acc[0]), "+f"(acc[1]), "+f"(acc[2]), "+f"(acc[3])
        : "r"(a[0]), "r"(a[1]), "r"(a[2]), "r"(a[3]), "r"(b[0]), "r"(b[1]));
}
__device__ __forceinline__ uint32_t packbf(float x, float y){
    __nv_bfloat162 t = __float22bfloat162_rn(make_float2(x, y));
    return *(uint32_t*)&t;
}
__device__ __forceinline__ float bfhi(float x){
    return __bfloat162float(__float2bfloat16(x));
}

// per-lane ldmatrix row-offset helpers (byte offsets within a tile):
__device__ __forceinline__ uint32_t lm_offA(int lane, int rowb){
    return (uint32_t)(((lane & 7) + ((lane >> 3) & 1)*8) * rowb + (lane >> 4)*16);
}
__device__ __forceinline__ uint32_t lm_offB(int lane, int rowb){
    return (uint32_t)(((lane & 7) + (lane >> 4)*8) * rowb + ((lane >> 3) & 1)*16);
}

// ---------------------------------------------------------------------------
// Pre-pass: split x fp32 -> bf16 hi/lo
// ---------------------------------------------------------------------------
__global__ void convert_split_x(const float* __restrict__ src)
{
    const int i = blockIdx.x * blockDim.x + threadIdx.x;   // float4 index
    const int n4 = (M_*C_) / 4;
    if (i >= n4) return;
    const float4 v = ((const float4*)src)[i];
    const float h0 = bfhi(v.x), h1 = bfhi(v.y), h2 = bfhi(v.z), h3 = bfhi(v.w);
    ((uint32_t*)g_XH)[i*2    ] = packbf(v.x, v.y);
    ((uint32_t*)g_XH)[i*2 + 1] = packbf(v.z, v.w);
    ((uint32_t*)g_XL)[i*2    ] = packbf(v.x - h0, v.y - h1);
    ((uint32_t*)g_XL)[i*2 + 1] = packbf(v.z - h2, v.w - h3);
}

// ---------------------------------------------------------------------------
// Pre-pass: transpose + split weights -> [N][768] bf16 hi/lo (K-major)
// ---------------------------------------------------------------------------
template<int WHICH>
__global__ void transpose_split(const float* __restrict__ w)
{
    constexpr int N = (WHICH == 0) ? 3*C_ : C_;
    __nv_bfloat16* Hh = (WHICH == 0) ? g_WaH : g_WpH;
    __nv_bfloat16* Ll = (WHICH == 0) ? g_WaL : g_WpL;

    __shared__ float tile[32][33];
    const int nb = blockIdx.x * 32;
    const int kb = blockIdx.y * 32;
    const int tx = threadIdx.x;
    const int ty = threadIdx.y;

    #pragma unroll
    for (int i = ty; i < 32; i += 8)
        tile[i][tx] = w[(size_t)(kb + i) * N + nb + tx];
    __syncthreads();

    #pragma unroll
    for (int i = ty; i < 32; i += 8){
        const float v = tile[tx][i];
        const __nv_bfloat16 h = __float2bfloat16(v);
        const __nv_bfloat16 l = __float2bfloat16(v - __bfloat162float(h));
        const size_t o = (size_t)(nb + i) * C_ + kb + tx;
        Hh[o] = h;
        Ll[o] = l;
    }
}

// ---------------------------------------------------------------------------
// Tensor-core GEMM (bf16 hi/lo, 3-pass compensation).
// CTA tile 256x128, 8 warps (4m x 2n), warp tile 64x64 -> 128 acc regs,
// 32 independent MMA chains per warp, HMMA:LDSM = 6:1. occ 1 by design.
// MODE 1: A=XH/XL, B=WaH/WaL -> scatter bf16 hi/lo into Qh/Ql,Kh/Kl,Vh/Vl(T)
// MODE 0: A=YH/YL, B=WpH/WpL -> fp32 Cout (d_out)
// ---------------------------------------------------------------------------
constexpr int ROWB   = 80;                 // bytes per smem row (32 bf16 + pad)
constexpr int A_MATB = 256 * ROWB;         // 20480 B (A tile, 256 rows)
constexpr int B_MATB = 128 * ROWB;         // 10240 B (B tile, 128 rows)
constexpr int ST_AH  = 0;
constexpr int ST_AL  = A_MATB;             // 20480
constexpr int ST_BH  = 2*A_MATB;           // 40960
constexpr int ST_BL  = 2*A_MATB + B_MATB;  // 51200
constexpr int STAGEB = 2*A_MATB + 2*B_MATB;// 61440
constexpr int GEMM_SMEM = 2 * STAGEB;      // 122880 B

template<int MODE>
__global__ __launch_bounds__(256, 1)
void mma_gemm(const float* __restrict__ bias, float* __restrict__ Cout)
{
    extern __shared__ __align__(128) uint8_t smem[];

    const __nv_bfloat16* AH = (MODE == 1) ? g_XH : g_YH;
    const __nv_bfloat16* AL = (MODE == 1) ? g_XL : g_YL;
    const __nv_bfloat16* BH = (MODE == 1) ? g_WaH : g_WpH;
    const __nv_bfloat16* BL = (MODE == 1) ? g_WaL : g_WpL;

    const int tid  = threadIdx.x;
    const int lane = tid & 31;
    const int warp = tid >> 5;
    const int wm   = warp >> 1;      // 0..3 -> m offset wm*64
    const int wn   = warp & 1;       // 0..1 -> n offset wn*64
    const int bc   = blockIdx.x;
    const int br   = blockIdx.y;

    const uint32_t sb = smem_u32(smem);

    auto load_stage = [&](int kt, int s){
        const uint32_t st = sb + (uint32_t)s * STAGEB;
        // A hi/lo: 256 rows x 4 chunks = 1024 chunks
        #pragma unroll
        for (int j = 0; j < 4; j++){
            const int ch  = tid + j*256;
            const int row = ch >> 2;
            const int cc  = ch & 3;
            const uint32_t so = (uint32_t)(row*ROWB + cc*16);
            const size_t ga = (size_t)(br*256 + row) * C_ + kt*32 + cc*8;
            cpa16(st + ST_AH + so, AH + ga);
            cpa16(st + ST_AL + so, AL + ga);
        }
        // B hi/lo: 128 rows x 4 chunks = 512 chunks
        #pragma unroll
        for (int j = 0; j < 2; j++){
            const int ch  = tid + j*256;
            const int row = ch >> 2;
            const int cc  = ch & 3;
            const uint32_t so = (uint32_t)(row*ROWB + cc*16);
            const size_t gb = (size_t)(bc*128 + row) * C_ + kt*32 + cc*8;
            cpa16(st + ST_BH + so, BH + gb);
            cpa16(st + ST_BL + so, BL + gb);
        }
        asm volatile("cp.async.commit_group;");
    };

    float acc[4][8][4];
    #pragma unroll
    for (int i = 0; i < 4; i++)
        #pragma unroll
        for (int j = 0; j < 8; j++)
            #pragma unroll
            for (int q = 0; q < 4; q++) acc[i][j][q] = 0.f;

    constexpr int NK = C_ / 32;    // 24

    load_stage(0, 0);
    asm volatile("cp.async.wait_group 0;");
    __syncthreads();

    const uint32_t offA = lm_offA(lane, ROWB) + (uint32_t)(wm*64)*ROWB + ST_AH;
    const uint32_t offB = lm_offB(lane, ROWB) + (uint32_t)(wn*64)*ROWB + ST_BH;

    for (int kt = 0; kt < NK; kt++){
        const int cur = kt & 1;
        if (kt + 1 < NK) load_stage(kt + 1, cur ^ 1);

        const uint32_t st = sb + (uint32_t)cur * STAGEB;

        #pragma unroll
        for (int kk = 0; kk < 2; kk++){
            // B fragments for this kk: 8 j-blocks hi + lo
            uint32_t bh[8][2], bl[8][2];
            #pragma unroll
            for (int jp = 0; jp < 4; jp++){
                const uint32_t ab = st + offB + (uint32_t)(jp*16)*ROWB + kk*32;
                ldsm4(bh[2*jp][0], bh[2*jp][1], bh[2*jp+1][0], bh[2*jp+1][1], ab);
                ldsm4(bl[2*jp][0], bl[2*jp][1], bl[2*jp+1][0], bl[2*jp+1][1],
                      ab + (uint32_t)(ST_BL - ST_BH));
            }
            // stream A row-blocks
            #pragma unroll
            for (int i = 0; i < 4; i++){
                const uint32_t aa = st + offA + (uint32_t)(i*16)*ROWB + kk*32;
                uint32_t ah[4], al[4];
                ldsm4(ah[0], ah[1], ah[2], ah[3], aa);
                ldsm4(al[0], al[1], al[2], al[3], aa + (uint32_t)(ST_AL - ST_AH));
                #pragma unroll
                for (int j = 0; j < 8; j++) mma16816(acc[i][j], ah, bh[j]);
                #pragma unroll
                for (int j = 0; j < 8; j++) mma16816(acc[i][j], ah, bl[j]);
                #pragma unroll
                for (int j = 0; j < 8; j++) mma16816(acc[i][j], al, bh[j]);
            }
        }

        if (kt + 1 < NK) asm volatile("cp.async.wait_group 0;");
        __syncthreads();
    }

    const int r  = lane >> 2;
    const int c4 = lane & 3;

    // Epilogue
    #pragma unroll
    for (int j = 0; j < 8; j++){
        const int col = bc*128 + wn*64 + j*8 + c4*2;
        const float2 bv = *(const float2*)&bias[col];
        if (MODE == 0){
            #pragma unroll
            for (int i = 0; i < 4; i++){
                const int row0 = br*256 + wm*64 + i*16 + r;
                float2 v0 = make_float2(acc[i][j][0] + bv.x, acc[i][j][1] + bv.y);
                float2 v1 = make_float2(acc[i][j][2] + bv.x, acc[i][j][3] + bv.y);
                *(float2*)&Cout[(size_t)row0     * C_ + col] = v0;
                *(float2*)&Cout[(size_t)(row0+8) * C_ + col] = v1;
            }
        } else {
            const int which = col / C_;
            const int rem   = col - which * C_;
            const int hh = rem >> 6;
            const int dd = rem & 63;
            #pragma unroll
            for (int i = 0; i < 4; i++){
                const int row0 = br*256 + wm*64 + i*16 + r;
                const int b0i = row0 >> 10, t0i = row0 & 1023;
                const int row1 = row0 + 8;
                const int b1i = row1 >> 10, t1i = row1 & 1023;
                float v00 = acc[i][j][0] + bv.x, v01 = acc[i][j][1] + bv.y;
                float v10 = acc[i][j][2] + bv.x, v11 = acc[i][j][3] + bv.y;
                if (which == 0){ v00*=0.125f; v01*=0.125f; v10*=0.125f; v11*=0.125f; }
                if (which < 2){
                    __nv_bfloat16* DH = (which == 0) ? g_Qh : g_Kh;
                    __nv_bfloat16* DL = (which == 0) ? g_Ql : g_Kl;
                    const size_t o0 = ((size_t)(b0i*H_ + hh)*T_ + t0i)*HS_ + dd;
                    const size_t o1 = ((size_t)(b1i*H_ + hh)*T_ + t1i)*HS_ + dd;
                    *(uint32_t*)&DH[o0] = packbf(v00, v01);
                    *(uint32_t*)&DL[o0] = packbf(v00 - bfhi(v00), v01 - bfhi(v01));
                    *(uint32_t*)&DH[o1] = packbf(v10, v11);
                    *(uint32_t*)&DL[o1] = packbf(v10 - bfhi(v10), v11 - bfhi(v11));
                } else {
                    const size_t vb0 = ((size_t)(b0i*H_ + hh)*HS_ + dd)*T_;
                    const size_t vb1 = ((size_t)(b1i*H_ + hh)*HS_ + dd)*T_;
                    g_Vh[vb0      + t0i] = __float2bfloat16(v00);
                    g_Vh[vb0 + T_ + t0i] = __float2bfloat16(v01);
                    g_Vh[vb1      + t1i] = __float2bfloat16(v10);
                    g_Vh[vb1 + T_ + t1i] = __float2bfloat16(v11);
                    g_Vl[vb0      + t0i] = __float2bfloat16(v00 - bfhi(v00));
                    g_Vl[vb0 + T_ + t0i] = __float2bfloat16(v01 - bfhi(v01));
                    g_Vl[vb1      + t1i] = __float2bfloat16(v10 - bfhi(v10));
                    g_Vl[vb1 + T_ + t1i] = __float2bfloat16(v11 - bfhi(v11));
                }
            }
        }
    }
}

// ---------------------------------------------------------------------------
// Tensor-core causal flash attention (unchanged from R7/R8 passing kernel).
// ---------------------------------------------------------------------------
constexpr int AT_ROWK = 144;
constexpr int AT_ROWV = 272;
constexpr int AT_MK   = 128 * AT_ROWK;
constexpr int AT_MV   = 64  * AT_ROWV;
constexpr int AT_Q    = 2 * AT_MK;
constexpr int AT_STAGE= 2*AT_MK + 2*AT_MV;
constexpr int ATTN_SMEM = AT_Q + 2*AT_STAGE;   // 180224

__global__ __launch_bounds__(256, 1)
void attn_tc()
{
    extern __shared__ __align__(128) uint8_t smx[];
    const uint32_t sb = smem_u32(smx);

    const int qt  = blockIdx.x;
    const int bh  = blockIdx.y;
    const int tid = threadIdx.x;
    const int lane = tid & 31;
    const int w    = tid >> 5;
    const int r    = lane >> 2;
    const int c4   = lane & 3;

    const size_t qoff = ((size_t)bh*T_ + qt*128) * HS_;
    #pragma unroll
    for (int j = 0; j < 4; j++){
        const int ch = tid + 256*j;
        const int row = ch >> 3, c = ch & 7;
        const uint32_t so = sb + (uint32_t)(row*AT_ROWK + c*16);
        const size_t g = qoff + (size_t)row*HS_ + c*8;
        cpa16(so,         g_Qh + g);
        cpa16(so + AT_MK, g_Ql + g);
    }

    auto load_kv = [&](int kt, int s){
        const uint32_t st = sb + AT_Q + (uint32_t)s * AT_STAGE;
        const size_t koff = ((size_t)bh*T_ + kt*128) * HS_;
        #pragma unroll
        for (int j = 0; j < 4; j++){
            const int ch = tid + 256*j;
            const int row = ch >> 3, c = ch & 7;
            const uint32_t so = st + (uint32_t)(row*AT_ROWK + c*16);
            const size_t g = koff + (size_t)row*HS_ + c*8;
            cpa16(so,         g_Kh + g);
            cpa16(so + AT_MK, g_Kl + g);
        }
        const size_t voff = (size_t)bh*HS_*T_ + kt*128;
        #pragma unroll
        for (int j = 0; j < 4; j++){
            const int ch = tid + 256*j;
            const int row = ch >> 4, c = ch & 15;
            const uint32_t so = st + 2*AT_MK + (uint32_t)(row*AT_ROWV + c*16);
            const size_t g = voff + (size_t)row*T_ + c*8;
            cpa16(so,         g_Vh + g);
            cpa16(so + AT_MV, g_Vl + g);
        }
        asm volatile("cp.async.commit_group;");
    };

    load_kv(0, 0);

    float m0 = -1e30f, m1 = -1e30f, l0 = 0.f, l1 = 0.f;
    float o[8][4];
    #pragma unroll
    for (int j2 = 0; j2 < 8; j2++)
        #pragma unroll
        for (int q = 0; q < 4; q++) o[j2][q] = 0.f;

    const uint32_t offQ = lm_offA(lane, AT_ROWK) + (uint32_t)(w*16)*AT_ROWK;
    const uint32_t offK = lm_offB(lane, AT_ROWK);
    const uint32_t offV = lm_offB(lane, AT_ROWV);

    for (int kt = 0; kt <= qt; kt++){
        if (kt < qt){
            load_kv(kt + 1, (kt + 1) & 1);
            asm volatile("cp.async.wait_group 1;");
        } else {
            asm volatile("cp.async.wait_group 0;");
        }
        __syncthreads();

        const uint32_t st = sb + AT_Q + (uint32_t)(kt & 1) * AT_STAGE;

        float s[16][4];
        #pragma unroll
        for (int j = 0; j < 16; j++){
            s[j][0] = s[j][1] = s[j][2] = s[j][3] = 0.f;
        }
        #pragma unroll
        for (int kk = 0; kk < 4; kk++){
            uint32_t qh[4], ql[4];
            {
                const uint32_t qa = sb + offQ + kk*32;
                ldsm4(qh[0], qh[1], qh[2], qh[3], qa);
                ldsm4(ql[0], ql[1], ql[2], ql[3], qa + AT_MK);
            }
            #pragma unroll
            for (int jq = 0; jq < 4; jq++){
                const uint32_t ka = st + offK + (uint32_t)(jq*32)*AT_ROWK + kk*32;
                uint32_t kh[4][2], kl[4][2];
                ldsm4(kh[0][0], kh[0][1], kh[1][0], kh[1][1], ka);
                ldsm4(kh[2][0], kh[2][1], kh[3][0], kh[3][1],
                      ka + (uint32_t)16*AT_ROWK);
                ldsm4(kl[0][0], kl[0][1], kl[1][0], kl[1][1], ka + AT_MK);
                ldsm4(kl[2][0], kl[2][1], kl[3][0], kl[3][1],
                      ka + AT_MK + (uint32_t)16*AT_ROWK);
                float* s0 = s[4*jq + 0]; float* s1 = s[4*jq + 1];
                float* s2 = s[4*jq + 2]; float* s3 = s[4*jq + 3];
                mma16816(s0, qh, kh[0]); mma16816(s1, qh, kh[1]);
                mma16816(s2, qh, kh[2]); mma16816(s3, qh, kh[3]);
                mma16816(s0, qh, kl[0]); mma16816(s1, qh, kl[1]);
                mma16816(s2, qh, kl[2]); mma16816(s3, qh, kl[3]);
                mma16816(s0, ql, kh[0]); mma16816(s1, ql, kh[1]);
                mma16816(s2, ql, kh[2]); mma16816(s3, ql, kh[3]);
            }
        }

        if (kt == qt){
            const int row0 = w*16 + r;
            #pragma unroll
            for (int j = 0; j < 16; j++){
                const int col0 = j*8 + c4*2;
                if (col0     > row0    ) s[j][0] = -1e30f;
                if (col0 + 1 > row0    ) s[j][1] = -1e30f;
                if (col0     > row0 + 8) s[j][2] = -1e30f;
                if (col0 + 1 > row0 + 8) s[j][3] = -1e30f;
            }
        }

        float rm0 = -1e30f, rm1 = -1e30f;
        #pragma unroll
        for (int j = 0; j < 16; j++){
            rm0 = fmaxf(rm0, fmaxf(s[j][0], s[j][1]));
            rm1 = fmaxf(rm1, fmaxf(s[j][2], s[j][3]));
        }
        rm0 = fmaxf(rm0, __shfl_xor_sync(0xffffffffu, rm0, 1));
        rm0 = fmaxf(rm0, __shfl_xor_sync(0xffffffffu, rm0, 2));
        rm1 = fmaxf(rm1, __shfl_xor_sync(0xffffffffu, rm1, 1));
        rm1 = fmaxf(rm1, __shfl_xor_sync(0xffffffffu, rm1, 2));
        const float mn0 = fmaxf(m0, rm0), mn1 = fmaxf(m1, rm1);
        const float a0 = __expf(m0 - mn0), a1 = __expf(m1 - mn1);
        m0 = mn0; m1 = mn1;
        float rs0 = 0.f, rs1 = 0.f;
        #pragma unroll
        for (int j = 0; j < 16; j++){
            s[j][0] = __expf(s[j][0] - mn0);
            s[j][1] = __expf(s[j][1] - mn0);
            s[j][2] = __expf(s[j][2] - mn1);
            s[j][3] = __expf(s[j][3] - mn1);
            rs0 += s[j][0] + s[j][1];
            rs1 += s[j][2] + s[j][3];
        }
        rs0 += __shfl_xor_sync(0xffffffffu, rs0, 1);
        rs0 += __shfl_xor_sync(0xffffffffu, rs0, 2);
        rs1 += __shfl_xor_sync(0xffffffffu, rs1, 1);
        rs1 += __shfl_xor_sync(0xffffffffu, rs1, 2);
        l0 = l0*a0 + rs0;
        l1 = l1*a1 + rs1;
        #pragma unroll
        for (int j2 = 0; j2 < 8; j2++){
            o[j2][0] *= a0; o[j2][1] *= a0;
            o[j2][2] *= a1; o[j2][3] *= a1;
        }

        const uint32_t vbase = st + 2*AT_MK;
        #pragma unroll
        for (int kk = 0; kk < 8; kk++){
            float ph[8], pl[8];
            #pragma unroll
            for (int e = 0; e < 4; e++){
                ph[e]   = bfhi(s[2*kk  ][e]);  pl[e]   = s[2*kk  ][e] - ph[e];
                ph[4+e] = bfhi(s[2*kk+1][e]);  pl[4+e] = s[2*kk+1][e] - ph[4+e];
            }
            uint32_t a_h[4], a_l[4];
            a_h[0] = packbf(ph[0], ph[1]);  a_h[1] = packbf(ph[2], ph[3]);
            a_h[2] = packbf(ph[4], ph[5]);  a_h[3] = packbf(ph[6], ph[7]);
            a_l[0] = packbf(pl[0], pl[1]);  a_l[1] = packbf(pl[2], pl[3]);
            a_l[2] = packbf(pl[4], pl[5]);  a_l[3] = packbf(pl[6], pl[7]);
            #pragma unroll
            for (int jq = 0; jq < 2; jq++){
                const uint32_t va = vbase + offV + (uint32_t)(jq*32)*AT_ROWV
                                  + kk*32;
                uint32_t vh[4][2], vl[4][2];
                ldsm4(vh[0][0], vh[0][1], vh[1][0], vh[1][1], va);
                ldsm4(vh[2][0], vh[2][1], vh[3][0], vh[3][1],
                      va + (uint32_t)16*AT_ROWV);
                ldsm4(vl[0][0], vl[0][1], vl[1][0], vl[1][1], va + AT_MV);
                ldsm4(vl[2][0], vl[2][1], vl[3][0], vl[3][1],
                      va + AT_MV + (uint32_t)16*AT_ROWV);
                float* o0 = o[4*jq + 0]; float* o1 = o[4*jq + 1];
                float* o2 = o[4*jq + 2]; float* o3 = o[4*jq + 3];
                mma16816(o0, a_h, vh[0]); mma16816(o1, a_h, vh[1]);
                mma16816(o2, a_h, vh[2]); mma16816(o3, a_h, vh[3]);
                mma16816(o0, a_h, vl[0]); mma16816(o1, a_h, vl[1]);
                mma16816(o2, a_h, vl[2]); mma16816(o3, a_h, vl[3]);
                mma16816(o0, a_l, vh[0]); mma16816(o1, a_l, vh[1]);
                mma16816(o2, a_l, vh[2]); mma16816(o3, a_l, vh[3]);
            }
        }
        __syncthreads();
    }

    const float inv0 = 1.f / l0, inv1 = 1.f / l1;
    const int bq = bh / H_, hh = bh % H_;
    const int t0 = qt*128 + w*16 + r;
    #pragma unroll
    for (int j2 = 0; j2 < 8; j2++){
        const int cc = hh*64 + j2*8 + c4*2;
        const float y0 = o[j2][0]*inv0, y1 = o[j2][1]*inv0;
        const float y2 = o[j2][2]*inv1, y3 = o[j2][3]*inv1;
        const size_t r0 = (size_t)(bq*T_ + t0    )*C_ + cc;
        const size_t r1 = (size_t)(bq*T_ + t0 + 8)*C_ + cc;
        *(uint32_t*)&g_YH[r0] = packbf(y0, y1);
        *(uint32_t*)&g_YL[r0] = packbf(y0 - bfhi(y0), y1 - bfhi(y1));
        *(uint32_t*)&g_YH[r1] = packbf(y2, y3);
        *(uint32_t*)&g_YL[r1] = packbf(y2 - bfhi(y2), y3 - bfhi(y3));
    }
}

// ---------------------------------------------------------------------------
extern "C" void kernel_launch(void* const* d_in, const int* in_sizes, int n_in,
                              void* d_out, int out_size)
{
    const float* x      = (const float*)d_in[0];
    const float* w_attn = (const float*)d_in[1];
    const float* b_attn = (const float*)d_in[2];
    const float* w_proj = (const float*)d_in[3];
    const float* b_proj = (const float*)d_in[4];
    float* out = (float*)d_out;

    cudaFuncSetAttribute(mma_gemm<1>, cudaFuncAttributeMaxDynamicSharedMemorySize, GEMM_SMEM);
    cudaFuncSetAttribute(mma_gemm<0>, cudaFuncAttributeMaxDynamicSharedMemorySize, GEMM_SMEM);
    cudaFuncSetAttribute(attn_tc, cudaFuncAttributeMaxDynamicSharedMemorySize, ATTN_SMEM);

    convert_split_x<<<(M_*C_/4 + 255)/256, 256>>>(x);
    transpose_split<0><<<dim3(3*C_/32, C_/32), dim3(32, 8)>>>(w_attn);
    transpose_split<1><<<dim3(C_/32,   C_/32), dim3(32, 8)>>>(w_proj);

    // QKV: grid 18 x 32 (256-row tiles)
    mma_gemm<1><<<dim3(3*C_/128, M_/256), 256, GEMM_SMEM>>>(b_attn, nullptr);
    attn_tc<<<dim3(T_/128, B_*H_), 256, ATTN_SMEM>>>();
    // proj: grid 6 x 32
    mma_gemm<0><<<dim3(C_/128, M_/256), 256, GEMM_SMEM>>>(b_proj, out);
}

// round 10
// speedup vs baseline: 1.0761x; 1.0761x over previous
#include <cuda_runtime.h>
#include <cuda_bf16.h>
#include <cstdint>

// Problem constants
#define B_  8
#define T_  1024
#define C_  768
#define H_  12
#define HS_ 64
#define M_  8192   // B*T

// ---------------------------------------------------------------------------
// Device-global scratch (no runtime allocation allowed)
// ---------------------------------------------------------------------------
__device__ __nv_bfloat16 g_XH[(size_t)M_*C_], g_XL[(size_t)M_*C_];
__device__ __nv_bfloat16 g_YH[(size_t)M_*C_], g_YL[(size_t)M_*C_];
__device__ __nv_bfloat16 g_WaH[(size_t)3*C_*C_], g_WaL[(size_t)3*C_*C_];
__device__ __nv_bfloat16 g_WpH[(size_t)C_*C_],   g_WpL[(size_t)C_*C_];

// Q/K: [B,H,T,hs] bf16 hi/lo (Q prescaled by 0.125). V: TRANSPOSED [B,H,hs,T].
__device__ __nv_bfloat16 g_Qh[B_*H_*T_*HS_], g_Ql[B_*H_*T_*HS_];
__device__ __nv_bfloat16 g_Kh[B_*H_*T_*HS_], g_Kl[B_*H_*T_*HS_];
__device__ __nv_bfloat16 g_Vh[B_*H_*T_*HS_], g_Vl[B_*H_*T_*HS_];

// ---------------------------------------------------------------------------
// Helpers (portable PTX only — compiles for plain sm_103 target)
// ---------------------------------------------------------------------------
__device__ __forceinline__ uint32_t smem_u32(const void* p){
    return (uint32_t)__cvta_generic_to_shared(p);
}
__device__ __forceinline__ void cpa16(uint32_t d, const void* s){
    asm volatile("cp.async.cg.shared.global [%0], [%1], 16;" :: "r"(d), "l"(s));
}
__device__ __forceinline__ void ldsm4(uint32_t& r0, uint32_t& r1,
                                      uint32_t& r2, uint32_t& r3, uint32_t a){
    asm volatile("ldmatrix.sync.aligned.m8n8.x4.shared.b16 {%0,%1,%2,%3}, [%4];"
                 : "=r"(r0), "=r"(r1), "=r"(r2), "=r"(r3) : "r"(a));
}
__device__ __forceinline__ void mma16816(float acc[4], const uint32_t a[4],
                                         const uint32_t b[2]){
    asm volatile(
        "mma.sync.aligned.m16n8k16.row.col.f32.bf16.bf16.f32 "
        "{%0,%1,%2,%3}, {%4,%5,%6,%7}, {%8,%9}, {%0,%1,%2,%3};"
        : "+f"(acc[0]), "+f"(acc[1]), "+f"(acc[2]), "+f"(acc[3])
        : "r"(a[0]), "r"(a[1]), "r"(a[2]), "r"(a[3]), "r"(b[0]), "r"(b[1]));
}
__device__ __forceinline__ uint32_t packbf(float x, float y){
    __nv_bfloat162 t = __float22bfloat162_rn(make_float2(x, y));
    return *(uint32_t*)&t;
}
__device__ __forceinline__ float bfhi(float x){
    return __bfloat162float(__float2bfloat16(x));
}

// per-lane ldmatrix row-offset helpers (byte offsets within a tile):
__device__ __forceinline__ uint32_t lm_offA(int lane, int rowb){
    return (uint32_t)(((lane & 7) + ((lane >> 3) & 1)*8) * rowb + (lane >> 4)*16);
}
__device__ __forceinline__ uint32_t lm_offB(int lane, int rowb){
    return (uint32_t)(((lane & 7) + (lane >> 4)*8) * rowb + ((lane >> 3) & 1)*16);
}

// ---------------------------------------------------------------------------
// Pre-pass: split x fp32 -> bf16 hi/lo
// ---------------------------------------------------------------------------
__global__ void convert_split_x(const float* __restrict__ src)
{
    const int i = blockIdx.x * blockDim.x + threadIdx.x;   // float4 index
    const int n4 = (M_*C_) / 4;
    if (i >= n4) return;
    const float4 v = ((const float4*)src)[i];
    const float h0 = bfhi(v.x), h1 = bfhi(v.y), h2 = bfhi(v.z), h3 = bfhi(v.w);
    ((uint32_t*)g_XH)[i*2    ] = packbf(v.x, v.y);
    ((uint32_t*)g_XH)[i*2 + 1] = packbf(v.z, v.w);
    ((uint32_t*)g_XL)[i*2    ] = packbf(v.x - h0, v.y - h1);
    ((uint32_t*)g_XL)[i*2 + 1] = packbf(v.z - h2, v.w - h3);
}

// ---------------------------------------------------------------------------
// Pre-pass: transpose + split weights -> [N][768] bf16 hi/lo (K-major)
// ---------------------------------------------------------------------------
template<int WHICH>
__global__ void transpose_split(const float* __restrict__ w)
{
    constexpr int N = (WHICH == 0) ? 3*C_ : C_;
    __nv_bfloat16* Hh = (WHICH == 0) ? g_WaH : g_WpH;
    __nv_bfloat16* Ll = (WHICH == 0) ? g_WaL : g_WpL;

    __shared__ float tile[32][33];
    const int nb = blockIdx.x * 32;
    const int kb = blockIdx.y * 32;
    const int tx = threadIdx.x;
    const int ty = threadIdx.y;

    #pragma unroll
    for (int i = ty; i < 32; i += 8)
        tile[i][tx] = w[(size_t)(kb + i) * N + nb + tx];
    __syncthreads();

    #pragma unroll
    for (int i = ty; i < 32; i += 8){
        const float v = tile[tx][i];
        const __nv_bfloat16 h = __float2bfloat16(v);
        const __nv_bfloat16 l = __float2bfloat16(v - __bfloat162float(h));
        const size_t o = (size_t)(nb + i) * C_ + kb + tx;
        Hh[o] = h;
        Ll[o] = l;
    }
}

// ---------------------------------------------------------------------------
// Tensor-core GEMM — exact R7 config (proven best: 248us QKV):
// 128x128 CTA tile, 8 warps (2m x 4n), occ 2, ldmatrix loads.
// ---------------------------------------------------------------------------
constexpr int ROWB   = 80;
constexpr int MATB   = 128 * ROWB;
constexpr int STAGEB = 4 * MATB;
constexpr int GEMM_SMEM = 2 * STAGEB;   // 81920 B

template<int MODE>
__global__ __launch_bounds__(256, 2)
void mma_gemm(const float* __restrict__ bias, float* __restrict__ Cout)
{
    extern __shared__ __align__(128) uint8_t smem[];

    const __nv_bfloat16* AH = (MODE == 1) ? g_XH : g_YH;
    const __nv_bfloat16* AL = (MODE == 1) ? g_XL : g_YL;
    const __nv_bfloat16* BH = (MODE == 1) ? g_WaH : g_WpH;
    const __nv_bfloat16* BL = (MODE == 1) ? g_WaL : g_WpL;

    const int tid  = threadIdx.x;
    const int lane = tid & 31;
    const int warp = tid >> 5;
    const int wm   = warp & 1;
    const int wn   = warp >> 1;
    const int bc   = blockIdx.x;
    const int br   = blockIdx.y;

    const uint32_t sb = smem_u32(smem);

    auto load_stage = [&](int kt, int s){
        const uint32_t st = sb + (uint32_t)s * STAGEB;
        #pragma unroll
        for (int j = 0; j < 2; j++){
            const int ch  = tid + j*256;
            const int row = ch >> 2;
            const int cc  = ch & 3;
            const uint32_t so = (uint32_t)(row*ROWB + cc*16);
            const size_t ga = (size_t)(br*128 + row) * C_ + kt*32 + cc*8;
            const size_t gb = (size_t)(bc*128 + row) * C_ + kt*32 + cc*8;
            cpa16(st            + so, AH + ga);
            cpa16(st +   MATB   + so, AL + ga);
            cpa16(st + 2*MATB   + so, BH + gb);
            cpa16(st + 3*MATB   + so, BL + gb);
        }
        asm volatile("cp.async.commit_group;");
    };

    float acc[4][4][4];
    #pragma unroll
    for (int i = 0; i < 4; i++)
        #pragma unroll
        for (int j = 0; j < 4; j++)
            #pragma unroll
            for (int q = 0; q < 4; q++) acc[i][j][q] = 0.f;

    constexpr int NK = C_ / 32;    // 24

    load_stage(0, 0);
    asm volatile("cp.async.wait_group 0;");
    __syncthreads();

    const uint32_t offA = lm_offA(lane, ROWB) + (uint32_t)(wm*64)*ROWB;
    const uint32_t offB = lm_offB(lane, ROWB) + (uint32_t)(wn*32)*ROWB + 2*MATB;

    for (int kt = 0; kt < NK; kt++){
        const int cur = kt & 1;
        if (kt + 1 < NK) load_stage(kt + 1, cur ^ 1);

        const uint32_t st = sb + (uint32_t)cur * STAGEB;

        #pragma unroll
        for (int kk = 0; kk < 2; kk++){
            uint32_t bh[4][2], bl[4][2];
            #pragma unroll
            for (int jp = 0; jp < 2; jp++){
                const uint32_t ab = st + offB + (uint32_t)(jp*16)*ROWB + kk*32;
                ldsm4(bh[2*jp][0], bh[2*jp][1], bh[2*jp+1][0], bh[2*jp+1][1], ab);
                ldsm4(bl[2*jp][0], bl[2*jp][1], bl[2*jp+1][0], bl[2*jp+1][1],
                      ab + MATB);
            }
            #pragma unroll
            for (int i = 0; i < 4; i++){
                const uint32_t aa = st + offA + (uint32_t)(i*16)*ROWB + kk*32;
                uint32_t ah[4], al[4];
                ldsm4(ah[0], ah[1], ah[2], ah[3], aa);
                ldsm4(al[0], al[1], al[2], al[3], aa + MATB);
                #pragma unroll
                for (int j = 0; j < 4; j++){
                    mma16816(acc[i][j], ah, bh[j]);
                    mma16816(acc[i][j], ah, bl[j]);
                    mma16816(acc[i][j], al, bh[j]);
                }
            }
        }

        if (kt + 1 < NK) asm volatile("cp.async.wait_group 0;");
        __syncthreads();
    }

    const int r  = lane >> 2;
    const int c4 = lane & 3;

    // Epilogue
    #pragma unroll
    for (int j = 0; j < 4; j++){
        const int col = bc*128 + wn*32 + j*8 + c4*2;
        const float2 bv = *(const float2*)&bias[col];
        if (MODE == 0){
            #pragma unroll
            for (int i = 0; i < 4; i++){
                const int row0 = br*128 + wm*64 + i*16 + r;
                float2 v0 = make_float2(acc[i][j][0] + bv.x, acc[i][j][1] + bv.y);
                float2 v1 = make_float2(acc[i][j][2] + bv.x, acc[i][j][3] + bv.y);
                *(float2*)&Cout[(size_t)row0     * C_ + col] = v0;
                *(float2*)&Cout[(size_t)(row0+8) * C_ + col] = v1;
            }
        } else {
            const int which = col / C_;
            const int rem   = col - which * C_;
            const int hh = rem >> 6;
            const int dd = rem & 63;
            #pragma unroll
            for (int i = 0; i < 4; i++){
                const int row0 = br*128 + wm*64 + i*16 + r;
                const int b0i = row0 >> 10, t0i = row0 & 1023;
                const int row1 = row0 + 8;
                const int b1i = row1 >> 10, t1i = row1 & 1023;
                float v00 = acc[i][j][0] + bv.x, v01 = acc[i][j][1] + bv.y;
                float v10 = acc[i][j][2] + bv.x, v11 = acc[i][j][3] + bv.y;
                if (which == 0){ v00*=0.125f; v01*=0.125f; v10*=0.125f; v11*=0.125f; }
                if (which < 2){
                    __nv_bfloat16* DH = (which == 0) ? g_Qh : g_Kh;
                    __nv_bfloat16* DL = (which == 0) ? g_Ql : g_Kl;
                    const size_t o0 = ((size_t)(b0i*H_ + hh)*T_ + t0i)*HS_ + dd;
                    const size_t o1 = ((size_t)(b1i*H_ + hh)*T_ + t1i)*HS_ + dd;
                    *(uint32_t*)&DH[o0] = packbf(v00, v01);
                    *(uint32_t*)&DL[o0] = packbf(v00 - bfhi(v00), v01 - bfhi(v01));
                    *(uint32_t*)&DH[o1] = packbf(v10, v11);
                    *(uint32_t*)&DL[o1] = packbf(v10 - bfhi(v10), v11 - bfhi(v11));
                } else {
                    const size_t vb0 = ((size_t)(b0i*H_ + hh)*HS_ + dd)*T_;
                    const size_t vb1 = ((size_t)(b1i*H_ + hh)*HS_ + dd)*T_;
                    g_Vh[vb0      + t0i] = __float2bfloat16(v00);
                    g_Vh[vb0 + T_ + t0i] = __float2bfloat16(v01);
                    g_Vh[vb1      + t1i] = __float2bfloat16(v10);
                    g_Vh[vb1 + T_ + t1i] = __float2bfloat16(v11);
                    g_Vl[vb0      + t0i] = __float2bfloat16(v00 - bfhi(v00));
                    g_Vl[vb0 + T_ + t0i] = __float2bfloat16(v01 - bfhi(v01));
                    g_Vl[vb1      + t1i] = __float2bfloat16(v10 - bfhi(v10));
                    g_Vl[vb1 + T_ + t1i] = __float2bfloat16(v11 - bfhi(v11));
                }
            }
        }
    }
}

// ---------------------------------------------------------------------------
// Tensor-core causal flash attention — k-tiles of 64 for OCCUPANCY 2.
// Q tile 128 rows (2 per warp of 16), K/V tiles 64 wide, double-buffered.
// smem: Q hi/lo 2x18432 + 2 stages x (K hi/lo 2x9216 + V hi/lo 2x9216)
//     = 36864 + 2*36864 = 110592 B  -> 2 CTAs/SM.
// Registers: s[8][4]+o[8][4]=64 acc + frags ~ 110 -> fits 128, no spills.
// ---------------------------------------------------------------------------
constexpr int AQ_ROW = 144;              // Q row: 64 d * 2B + 16 pad
constexpr int AK_ROW = 144;              // K row: 64 d * 2B + 16 pad
constexpr int AV_ROW = 144;              // V row: 64 t * 2B + 16 pad
constexpr int A_MQ   = 128 * AQ_ROW;     // 18432 per Q matrix (hi or lo)
constexpr int A_MK   = 64  * AK_ROW;     // 9216 per K matrix
constexpr int A_MV   = 64  * AV_ROW;     // 9216 per V matrix
constexpr int A_QTOT = 2 * A_MQ;         // 36864
constexpr int A_KH   = 0;
constexpr int A_KL   = A_MK;             // 9216
constexpr int A_VH   = 2*A_MK;           // 18432
constexpr int A_VL   = 2*A_MK + A_MV;    // 27648
constexpr int A_STG  = 2*A_MK + 2*A_MV;  // 36864
constexpr int ATTN_SMEM = A_QTOT + 2*A_STG;  // 110592

__global__ __launch_bounds__(256, 2)
void attn_tc()
{
    extern __shared__ __align__(128) uint8_t smx[];
    const uint32_t sb = smem_u32(smx);

    const int qt  = blockIdx.x;    // 0..7 (128-row q tiles)
    const int bh  = blockIdx.y;    // 0..95
    const int tid = threadIdx.x;
    const int lane = tid & 31;
    const int w    = tid >> 5;
    const int r    = lane >> 2;
    const int c4   = lane & 3;

    // ---- Q load (hi/lo), 128 rows ----
    const size_t qoff = ((size_t)bh*T_ + qt*128) * HS_;
    #pragma unroll
    for (int j = 0; j < 4; j++){
        const int ch = tid + 256*j;           // 0..1023
        const int row = ch >> 3, c = ch & 7;
        const uint32_t so = sb + (uint32_t)(row*AQ_ROW + c*16);
        const size_t g = qoff + (size_t)row*HS_ + c*8;
        cpa16(so,        g_Qh + g);
        cpa16(so + A_MQ, g_Ql + g);
    }

    auto load_kv = [&](int kt2, int s){
        const uint32_t st = sb + A_QTOT + (uint32_t)s * A_STG;
        const size_t koff = ((size_t)bh*T_ + kt2*64) * HS_;
        const size_t voff = (size_t)bh*HS_*T_ + kt2*64;
        #pragma unroll
        for (int j = 0; j < 2; j++){
            const int ch = tid + 256*j;       // 0..511
            const int row = ch >> 3, c = ch & 7;
            // K: rows = 64 tokens, cols = 64 d
            const uint32_t sk = st + (uint32_t)(row*AK_ROW + c*16);
            const size_t gk = koff + (size_t)row*HS_ + c*8;
            cpa16(sk + A_KH, g_Kh + gk);
            cpa16(sk + A_KL, g_Kl + gk);
            // V: rows = 64 d, cols = 64 tokens
            const uint32_t sv = st + (uint32_t)(row*AV_ROW + c*16);
            const size_t gv = voff + (size_t)row*T_ + c*8;
            cpa16(sv + A_VH, g_Vh + gv);
            cpa16(sv + A_VL, g_Vl + gv);
        }
        asm volatile("cp.async.commit_group;");
    };

    load_kv(0, 0);   // group 0 = Q + stage0

    float m0 = -1e30f, m1 = -1e30f, l0 = 0.f, l1 = 0.f;
    float o[8][4];
    #pragma unroll
    for (int j2 = 0; j2 < 8; j2++)
        #pragma unroll
        for (int q = 0; q < 4; q++) o[j2][q] = 0.f;

    const uint32_t offQ = lm_offA(lane, AQ_ROW) + (uint32_t)(w*16)*AQ_ROW;
    const uint32_t offK = lm_offB(lane, AK_ROW);
    const uint32_t offV = lm_offB(lane, AV_ROW);

    const int nkt = 2*(qt + 1);    // number of 64-wide k tiles

    for (int kt2 = 0; kt2 < nkt; kt2++){
        if (kt2 + 1 < nkt){
            load_kv(kt2 + 1, (kt2 + 1) & 1);
            asm volatile("cp.async.wait_group 1;");
        } else {
            asm volatile("cp.async.wait_group 0;");
        }
        __syncthreads();

        const uint32_t st = sb + A_QTOT + (uint32_t)(kt2 & 1) * A_STG;

        // ---- S = Q @ K^T (3-pass hi/lo), 64 k-rows ----
        float s[8][4];
        #pragma unroll
        for (int j = 0; j < 8; j++){
            s[j][0] = s[j][1] = s[j][2] = s[j][3] = 0.f;
        }
        #pragma unroll
        for (int kk = 0; kk < 4; kk++){           // d = 64 -> 4 k16 steps
            uint32_t qh[4], ql[4];
            {
                const uint32_t qa = sb + offQ + kk*32;
                ldsm4(qh[0], qh[1], qh[2], qh[3], qa);
                ldsm4(ql[0], ql[1], ql[2], ql[3], qa + A_MQ);
            }
            #pragma unroll
            for (int jq = 0; jq < 2; jq++){       // 32 k-rows per block
                const uint32_t ka = st + A_KH + offK
                                  + (uint32_t)(jq*32)*AK_ROW + kk*32;
                uint32_t kh[4][2], kl[4][2];
                ldsm4(kh[0][0], kh[0][1], kh[1][0], kh[1][1], ka);
                ldsm4(kh[2][0], kh[2][1], kh[3][0], kh[3][1],
                      ka + (uint32_t)16*AK_ROW);
                ldsm4(kl[0][0], kl[0][1], kl[1][0], kl[1][1], ka + A_MK);
                ldsm4(kl[2][0], kl[2][1], kl[3][0], kl[3][1],
                      ka + A_MK + (uint32_t)16*AK_ROW);
                float* s0 = s[4*jq + 0]; float* s1 = s[4*jq + 1];
                float* s2 = s[4*jq + 2]; float* s3 = s[4*jq + 3];
                mma16816(s0, qh, kh[0]); mma16816(s1, qh, kh[1]);
                mma16816(s2, qh, kh[2]); mma16816(s3, qh, kh[3]);
                mma16816(s0, qh, kl[0]); mma16816(s1, qh, kl[1]);
                mma16816(s2, qh, kl[2]); mma16816(s3, qh, kl[3]);
                mma16816(s0, ql, kh[0]); mma16816(s1, ql, kh[1]);
                mma16816(s2, ql, kh[2]); mma16816(s3, ql, kh[3]);
            }
        }

        // ---- causal mask (only the two diagonal-overlapping tiles) ----
        if (kt2 >= 2*qt){
            const int base = (kt2 - 2*qt)*64;     // 0 or 64
            const int row0 = w*16 + r;
            #pragma unroll
            for (int j = 0; j < 8; j++){
                const int col0 = base + j*8 + c4*2;
                if (col0     > row0    ) s[j][0] = -1e30f;
                if (col0 + 1 > row0    ) s[j][1] = -1e30f;
                if (col0     > row0 + 8) s[j][2] = -1e30f;
                if (col0 + 1 > row0 + 8) s[j][3] = -1e30f;
            }
        }

        // ---- online softmax ----
        float rm0 = -1e30f, rm1 = -1e30f;
        #pragma unroll
        for (int j = 0; j < 8; j++){
            rm0 = fmaxf(rm0, fmaxf(s[j][0], s[j][1]));
            rm1 = fmaxf(rm1, fmaxf(s[j][2], s[j][3]));
        }
        rm0 = fmaxf(rm0, __shfl_xor_sync(0xffffffffu, rm0, 1));
        rm0 = fmaxf(rm0, __shfl_xor_sync(0xffffffffu, rm0, 2));
        rm1 = fmaxf(rm1, __shfl_xor_sync(0xffffffffu, rm1, 1));
        rm1 = fmaxf(rm1, __shfl_xor_sync(0xffffffffu, rm1, 2));
        const float mn0 = fmaxf(m0, rm0), mn1 = fmaxf(m1, rm1);
        const float a0 = __expf(m0 - mn0), a1 = __expf(m1 - mn1);
        m0 = mn0; m1 = mn1;
        float rs0 = 0.f, rs1 = 0.f;
        #pragma unroll
        for (int j = 0; j < 8; j++){
            s[j][0] = __expf(s[j][0] - mn0);
            s[j][1] = __expf(s[j][1] - mn0);
            s[j][2] = __expf(s[j][2] - mn1);
            s[j][3] = __expf(s[j][3] - mn1);
            rs0 += s[j][0] + s[j][1];
            rs1 += s[j][2] + s[j][3];
        }
        rs0 += __shfl_xor_sync(0xffffffffu, rs0, 1);
        rs0 += __shfl_xor_sync(0xffffffffu, rs0, 2);
        rs1 += __shfl_xor_sync(0xffffffffu, rs1, 1);
        rs1 += __shfl_xor_sync(0xffffffffu, rs1, 2);
        l0 = l0*a0 + rs0;
        l1 = l1*a1 + rs1;
        #pragma unroll
        for (int j2 = 0; j2 < 8; j2++){
            o[j2][0] *= a0; o[j2][1] *= a0;
            o[j2][2] *= a1; o[j2][3] *= a1;
        }

        // ---- O += P @ V (3-pass: Ph*Vh + Ph*Vl + Pl*Vh) ----
        #pragma unroll
        for (int kk = 0; kk < 4; kk++){           // t = 64 -> 4 k16 steps
            float ph[8], pl[8];
            #pragma unroll
            for (int e = 0; e < 4; e++){
                ph[e]   = bfhi(s[2*kk  ][e]);  pl[e]   = s[2*kk  ][e] - ph[e];
                ph[4+e] = bfhi(s[2*kk+1][e]);  pl[4+e] = s[2*kk+1][e] - ph[4+e];
            }
            uint32_t a_h[4], a_l[4];
            a_h[0] = packbf(ph[0], ph[1]);  a_h[1] = packbf(ph[2], ph[3]);
            a_h[2] = packbf(ph[4], ph[5]);  a_h[3] = packbf(ph[6], ph[7]);
            a_l[0] = packbf(pl[0], pl[1]);  a_l[1] = packbf(pl[2], pl[3]);
            a_l[2] = packbf(pl[4], pl[5]);  a_l[3] = packbf(pl[6], pl[7]);
            #pragma unroll
            for (int jq = 0; jq < 2; jq++){       // 32 d-rows per block
                const uint32_t va = st + A_VH + offV
                                  + (uint32_t)(jq*32)*AV_ROW + kk*32;
                uint32_t vh[4][2], vl[4][2];
                ldsm4(vh[0][0], vh[0][1], vh[1][0], vh[1][1], va);
                ldsm4(vh[2][0], vh[2][1], vh[3][0], vh[3][1],
                      va + (uint32_t)16*AV_ROW);
                ldsm4(vl[0][0], vl[0][1], vl[1][0], vl[1][1], va + A_MV);
                ldsm4(vl[2][0], vl[2][1], vl[3][0], vl[3][1],
                      va + A_MV + (uint32_t)16*AV_ROW);
                float* o0 = o[4*jq + 0]; float* o1 = o[4*jq + 1];
                float* o2 = o[4*jq + 2]; float* o3 = o[4*jq + 3];
                mma16816(o0, a_h, vh[0]); mma16816(o1, a_h, vh[1]);
                mma16816(o2, a_h, vh[2]); mma16816(o3, a_h, vh[3]);
                mma16816(o0, a_h, vl[0]); mma16816(o1, a_h, vl[1]);
                mma16816(o2, a_h, vl[2]); mma16816(o3, a_h, vl[3]);
                mma16816(o0, a_l, vh[0]); mma16816(o1, a_l, vh[1]);
                mma16816(o2, a_l, vh[2]); mma16816(o3, a_l, vh[3]);
            }
        }
        __syncthreads();
    }

    // ---- epilogue: write YH/YL bf16 hi/lo [M][768] ----
    const float inv0 = 1.f / l0, inv1 = 1.f / l1;
    const int bq = bh / H_, hh = bh % H_;
    const int t0 = qt*128 + w*16 + r;
    #pragma unroll
    for (int j2 = 0; j2 < 8; j2++){
        const int cc = hh*64 + j2*8 + c4*2;
        const float y0 = o[j2][0]*inv0, y1 = o[j2][1]*inv0;
        const float y2 = o[j2][2]*inv1, y3 = o[j2][3]*inv1;
        const size_t r0 = (size_t)(bq*T_ + t0    )*C_ + cc;
        const size_t r1 = (size_t)(bq*T_ + t0 + 8)*C_ + cc;
        *(uint32_t*)&g_YH[r0] = packbf(y0, y1);
        *(uint32_t*)&g_YL[r0] = packbf(y0 - bfhi(y0), y1 - bfhi(y1));
        *(uint32_t*)&g_YH[r1] = packbf(y2, y3);
        *(uint32_t*)&g_YL[r1] = packbf(y2 - bfhi(y2), y3 - bfhi(y3));
    }
}

// ---------------------------------------------------------------------------
extern "C" void kernel_launch(void* const* d_in, const int* in_sizes, int n_in,
                              void* d_out, int out_size)
{
    const float* x      = (const float*)d_in[0];
    const float* w_attn = (const float*)d_in[1];
    const float* b_attn = (const float*)d_in[2];
    const float* w_proj = (const float*)d_in[3];
    const float* b_proj = (const float*)d_in[4];
    float* out = (float*)d_out;

    cudaFuncSetAttribute(mma_gemm<1>, cudaFuncAttributeMaxDynamicSharedMemorySize, GEMM_SMEM);
    cudaFuncSetAttribute(mma_gemm<0>, cudaFuncAttributeMaxDynamicSharedMemorySize, GEMM_SMEM);
    cudaFuncSetAttribute(attn_tc, cudaFuncAttributeMaxDynamicSharedMemorySize, ATTN_SMEM);

    convert_split_x<<<(M_*C_/4 + 255)/256, 256>>>(x);
    transpose_split<0><<<dim3(3*C_/32, C_/32), dim3(32, 8)>>>(w_attn);
    transpose_split<1><<<dim3(C_/32,   C_/32), dim3(32, 8)>>>(w_proj);

    mma_gemm<1><<<dim3(3*C_/128, M_/128), 256, GEMM_SMEM>>>(b_attn, nullptr);
    attn_tc<<<dim3(T_/128, B_*H_), 256, ATTN_SMEM>>>();
    mma_gemm<0><<<dim3(C_/128, M_/128), 256, GEMM_SMEM>>>(b_proj, out);
}

// round 11
// speedup vs baseline: 1.0773x; 1.0011x over previous
#include <cuda_runtime.h>
#include <cuda_bf16.h>
#include <cstdint>

// Problem constants
#define B_  8
#define T_  1024
#define C_  768
#define H_  12
#define HS_ 64
#define M_  8192   // B*T

// ---------------------------------------------------------------------------
// Device-global scratch (no runtime allocation allowed)
// ---------------------------------------------------------------------------
__device__ __nv_bfloat16 g_XH[(size_t)M_*C_], g_XL[(size_t)M_*C_];
__device__ __nv_bfloat16 g_YH[(size_t)M_*C_], g_YL[(size_t)M_*C_];
__device__ __nv_bfloat16 g_WaH[(size_t)3*C_*C_], g_WaL[(size_t)3*C_*C_];
__device__ __nv_bfloat16 g_WpH[(size_t)C_*C_],   g_WpL[(size_t)C_*C_];

// Q/K: [B,H,T,hs] bf16 hi/lo (Q prescaled by 0.125). V: TRANSPOSED [B,H,hs,T].
__device__ __nv_bfloat16 g_Qh[B_*H_*T_*HS_], g_Ql[B_*H_*T_*HS_];
__device__ __nv_bfloat16 g_Kh[B_*H_*T_*HS_], g_Kl[B_*H_*T_*HS_];
__device__ __nv_bfloat16 g_Vh[B_*H_*T_*HS_], g_Vl[B_*H_*T_*HS_];

// ---------------------------------------------------------------------------
// Helpers (portable PTX only — compiles for plain sm_103 target)
// ---------------------------------------------------------------------------
__device__ __forceinline__ uint32_t smem_u32(const void* p){
    return (uint32_t)__cvta_generic_to_shared(p);
}
__device__ __forceinline__ void cpa16(uint32_t d, const void* s){
    asm volatile("cp.async.cg.shared.global [%0], [%1], 16;" :: "r"(d), "l"(s));
}
__device__ __forceinline__ void ldsm4(uint32_t& r0, uint32_t& r1,
                                      uint32_t& r2, uint32_t& r3, uint32_t a){
    asm volatile("ldmatrix.sync.aligned.m8n8.x4.shared.b16 {%0,%1,%2,%3}, [%4];"
                 : "=r"(r0), "=r"(r1), "=r"(r2), "=r"(r3) : "r"(a));
}
__device__ __forceinline__ void mma16816(float acc[4], const uint32_t a[4],
                                         const uint32_t b[2]){
    asm volatile(
        "mma.sync.aligned.m16n8k16.row.col.f32.bf16.bf16.f32 "
        "{%0,%1,%2,%3}, {%4,%5,%6,%7}, {%8,%9}, {%0,%1,%2,%3};"
        : "+f"(acc[0]), "+f"(acc[1]), "+f"(acc[2]), "+f"(acc[3])
        : "r"(a[0]), "r"(a[1]), "r"(a[2]), "r"(a[3]), "r"(b[0]), "r"(b[1]));
}
__device__ __forceinline__ uint32_t packbf(float x, float y){
    __nv_bfloat162 t = __float22bfloat162_rn(make_float2(x, y));
    return *(uint32_t*)&t;
}
__device__ __forceinline__ float bfhi(float x){
    return __bfloat162float(__float2bfloat16(x));
}

// per-lane ldmatrix row-offset helpers (byte offsets within a tile):
__device__ __forceinline__ uint32_t lm_offA(int lane, int rowb){
    return (uint32_t)(((lane & 7) + ((lane >> 3) & 1)*8) * rowb + (lane >> 4)*16);
}
__device__ __forceinline__ uint32_t lm_offB(int lane, int rowb){
    return (uint32_t)(((lane & 7) + (lane >> 4)*8) * rowb + ((lane >> 3) & 1)*16);
}

// ---------------------------------------------------------------------------
// Pre-pass: split x fp32 -> bf16 hi/lo
// ---------------------------------------------------------------------------
__global__ void convert_split_x(const float* __restrict__ src)
{
    const int i = blockIdx.x * blockDim.x + threadIdx.x;   // float4 index
    const int n4 = (M_*C_) / 4;
    if (i >= n4) return;
    const float4 v = ((const float4*)src)[i];
    const float h0 = bfhi(v.x), h1 = bfhi(v.y), h2 = bfhi(v.z), h3 = bfhi(v.w);
    ((uint32_t*)g_XH)[i*2    ] = packbf(v.x, v.y);
    ((uint32_t*)g_XH)[i*2 + 1] = packbf(v.z, v.w);
    ((uint32_t*)g_XL)[i*2    ] = packbf(v.x - h0, v.y - h1);
    ((uint32_t*)g_XL)[i*2 + 1] = packbf(v.z - h2, v.w - h3);
}

// ---------------------------------------------------------------------------
// Pre-pass: transpose + split weights -> [N][768] bf16 hi/lo (K-major)
// ---------------------------------------------------------------------------
template<int WHICH>
__global__ void transpose_split(const float* __restrict__ w)
{
    constexpr int N = (WHICH == 0) ? 3*C_ : C_;
    __nv_bfloat16* Hh = (WHICH == 0) ? g_WaH : g_WpH;
    __nv_bfloat16* Ll = (WHICH == 0) ? g_WaL : g_WpL;

    __shared__ float tile[32][33];
    const int nb = blockIdx.x * 32;
    const int kb = blockIdx.y * 32;
    const int tx = threadIdx.x;
    const int ty = threadIdx.y;

    #pragma unroll
    for (int i = ty; i < 32; i += 8)
        tile[i][tx] = w[(size_t)(kb + i) * N + nb + tx];
    __syncthreads();

    #pragma unroll
    for (int i = ty; i < 32; i += 8){
        const float v = tile[tx][i];
        const __nv_bfloat16 h = __float2bfloat16(v);
        const __nv_bfloat16 l = __float2bfloat16(v - __bfloat162float(h));
        const size_t o = (size_t)(nb + i) * C_ + kb + tx;
        Hh[o] = h;
        Ll[o] = l;
    }
}

// ---------------------------------------------------------------------------
// Tensor-core GEMM — exact R7 config (proven best: 248us QKV):
// 128x128 CTA tile, 8 warps (2m x 4n), occ 2, ldmatrix loads.
// ---------------------------------------------------------------------------
constexpr int ROWB   = 80;
constexpr int MATB   = 128 * ROWB;
constexpr int STAGEB = 4 * MATB;
constexpr int GEMM_SMEM = 2 * STAGEB;   // 81920 B

template<int MODE>
__global__ __launch_bounds__(256, 2)
void mma_gemm(const float* __restrict__ bias, float* __restrict__ Cout)
{
    extern __shared__ __align__(128) uint8_t smem[];

    const __nv_bfloat16* AH = (MODE == 1) ? g_XH : g_YH;
    const __nv_bfloat16* AL = (MODE == 1) ? g_XL : g_YL;
    const __nv_bfloat16* BH = (MODE == 1) ? g_WaH : g_WpH;
    const __nv_bfloat16* BL = (MODE == 1) ? g_WaL : g_WpL;

    const int tid  = threadIdx.x;
    const int lane = tid & 31;
    const int warp = tid >> 5;
    const int wm   = warp & 1;
    const int wn   = warp >> 1;
    const int bc   = blockIdx.x;
    const int br   = blockIdx.y;

    const uint32_t sb = smem_u32(smem);

    auto load_stage = [&](int kt, int s){
        const uint32_t st = sb + (uint32_t)s * STAGEB;
        #pragma unroll
        for (int j = 0; j < 2; j++){
            const int ch  = tid + j*256;
            const int row = ch >> 2;
            const int cc  = ch & 3;
            const uint32_t so = (uint32_t)(row*ROWB + cc*16);
            const size_t ga = (size_t)(br*128 + row) * C_ + kt*32 + cc*8;
            const size_t gb = (size_t)(bc*128 + row) * C_ + kt*32 + cc*8;
            cpa16(st            + so, AH + ga);
            cpa16(st +   MATB   + so, AL + ga);
            cpa16(st + 2*MATB   + so, BH + gb);
            cpa16(st + 3*MATB   + so, BL + gb);
        }
        asm volatile("cp.async.commit_group;");
    };

    float acc[4][4][4];
    #pragma unroll
    for (int i = 0; i < 4; i++)
        #pragma unroll
        for (int j = 0; j < 4; j++)
            #pragma unroll
            for (int q = 0; q < 4; q++) acc[i][j][q] = 0.f;

    constexpr int NK = C_ / 32;    // 24

    load_stage(0, 0);
    asm volatile("cp.async.wait_group 0;");
    __syncthreads();

    const uint32_t offA = lm_offA(lane, ROWB) + (uint32_t)(wm*64)*ROWB;
    const uint32_t offB = lm_offB(lane, ROWB) + (uint32_t)(wn*32)*ROWB + 2*MATB;

    for (int kt = 0; kt < NK; kt++){
        const int cur = kt & 1;
        if (kt + 1 < NK) load_stage(kt + 1, cur ^ 1);

        const uint32_t st = sb + (uint32_t)cur * STAGEB;

        #pragma unroll
        for (int kk = 0; kk < 2; kk++){
            uint32_t bh[4][2], bl[4][2];
            #pragma unroll
            for (int jp = 0; jp < 2; jp++){
                const uint32_t ab = st + offB + (uint32_t)(jp*16)*ROWB + kk*32;
                ldsm4(bh[2*jp][0], bh[2*jp][1], bh[2*jp+1][0], bh[2*jp+1][1], ab);
                ldsm4(bl[2*jp][0], bl[2*jp][1], bl[2*jp+1][0], bl[2*jp+1][1],
                      ab + MATB);
            }
            #pragma unroll
            for (int i = 0; i < 4; i++){
                const uint32_t aa = st + offA + (uint32_t)(i*16)*ROWB + kk*32;
                uint32_t ah[4], al[4];
                ldsm4(ah[0], ah[1], ah[2], ah[3], aa);
                ldsm4(al[0], al[1], al[2], al[3], aa + MATB);
                #pragma unroll
                for (int j = 0; j < 4; j++){
                    mma16816(acc[i][j], ah, bh[j]);
                    mma16816(acc[i][j], ah, bl[j]);
                    mma16816(acc[i][j], al, bh[j]);
                }
            }
        }

        if (kt + 1 < NK) asm volatile("cp.async.wait_group 0;");
        __syncthreads();
    }

    const int r  = lane >> 2;
    const int c4 = lane & 3;

    // Epilogue
    #pragma unroll
    for (int j = 0; j < 4; j++){
        const int col = bc*128 + wn*32 + j*8 + c4*2;
        const float2 bv = *(const float2*)&bias[col];
        if (MODE == 0){
            #pragma unroll
            for (int i = 0; i < 4; i++){
                const int row0 = br*128 + wm*64 + i*16 + r;
                float2 v0 = make_float2(acc[i][j][0] + bv.x, acc[i][j][1] + bv.y);
                float2 v1 = make_float2(acc[i][j][2] + bv.x, acc[i][j][3] + bv.y);
                *(float2*)&Cout[(size_t)row0     * C_ + col] = v0;
                *(float2*)&Cout[(size_t)(row0+8) * C_ + col] = v1;
            }
        } else {
            const int which = col / C_;
            const int rem   = col - which * C_;
            const int hh = rem >> 6;
            const int dd = rem & 63;
            #pragma unroll
            for (int i = 0; i < 4; i++){
                const int row0 = br*128 + wm*64 + i*16 + r;
                const int b0i = row0 >> 10, t0i = row0 & 1023;
                const int row1 = row0 + 8;
                const int b1i = row1 >> 10, t1i = row1 & 1023;
                float v00 = acc[i][j][0] + bv.x, v01 = acc[i][j][1] + bv.y;
                float v10 = acc[i][j][2] + bv.x, v11 = acc[i][j][3] + bv.y;
                if (which == 0){ v00*=0.125f; v01*=0.125f; v10*=0.125f; v11*=0.125f; }
                if (which < 2){
                    __nv_bfloat16* DH = (which == 0) ? g_Qh : g_Kh;
                    __nv_bfloat16* DL = (which == 0) ? g_Ql : g_Kl;
                    const size_t o0 = ((size_t)(b0i*H_ + hh)*T_ + t0i)*HS_ + dd;
                    const size_t o1 = ((size_t)(b1i*H_ + hh)*T_ + t1i)*HS_ + dd;
                    *(uint32_t*)&DH[o0] = packbf(v00, v01);
                    *(uint32_t*)&DL[o0] = packbf(v00 - bfhi(v00), v01 - bfhi(v01));
                    *(uint32_t*)&DH[o1] = packbf(v10, v11);
                    *(uint32_t*)&DL[o1] = packbf(v10 - bfhi(v10), v11 - bfhi(v11));
                } else {
                    const size_t vb0 = ((size_t)(b0i*H_ + hh)*HS_ + dd)*T_;
                    const size_t vb1 = ((size_t)(b1i*H_ + hh)*HS_ + dd)*T_;
                    g_Vh[vb0      + t0i] = __float2bfloat16(v00);
                    g_Vh[vb0 + T_ + t0i] = __float2bfloat16(v01);
                    g_Vh[vb1      + t1i] = __float2bfloat16(v10);
                    g_Vh[vb1 + T_ + t1i] = __float2bfloat16(v11);
                    g_Vl[vb0      + t0i] = __float2bfloat16(v00 - bfhi(v00));
                    g_Vl[vb0 + T_ + t0i] = __float2bfloat16(v01 - bfhi(v01));
                    g_Vl[vb1      + t1i] = __float2bfloat16(v10 - bfhi(v10));
                    g_Vl[vb1 + T_ + t1i] = __float2bfloat16(v11 - bfhi(v11));
                }
            }
        }
    }
}

// ---------------------------------------------------------------------------
// Tensor-core causal flash attention — occ 2 (k-tiles of 64) with
// LOOP-INVARIANT Q FRAGMENTS CACHED IN REGISTERS (loaded once at kt2==0).
// smem 110592 B -> 2 CTAs/SM. Regs ~125 (s32 + o32 + Qfrag32 + transients).
// ---------------------------------------------------------------------------
constexpr int AQ_ROW = 144;
constexpr int AK_ROW = 144;
constexpr int AV_ROW = 144;
constexpr int A_MQ   = 128 * AQ_ROW;     // 18432
constexpr int A_MK   = 64  * AK_ROW;     // 9216
constexpr int A_MV   = 64  * AV_ROW;     // 9216
constexpr int A_QTOT = 2 * A_MQ;         // 36864
constexpr int A_KH   = 0;
constexpr int A_KL   = A_MK;
constexpr int A_VH   = 2*A_MK;
constexpr int A_VL   = 2*A_MK + A_MV;
constexpr int A_STG  = 2*A_MK + 2*A_MV;  // 36864
constexpr int ATTN_SMEM = A_QTOT + 2*A_STG;  // 110592

__global__ __launch_bounds__(256, 2)
void attn_tc()
{
    extern __shared__ __align__(128) uint8_t smx[];
    const uint32_t sb = smem_u32(smx);

    const int qt  = blockIdx.x;    // 0..7 (128-row q tiles)
    const int bh  = blockIdx.y;    // 0..95
    const int tid = threadIdx.x;
    const int lane = tid & 31;
    const int w    = tid >> 5;
    const int r    = lane >> 2;
    const int c4   = lane & 3;

    // ---- Q load (hi/lo), 128 rows ----
    const size_t qoff = ((size_t)bh*T_ + qt*128) * HS_;
    #pragma unroll
    for (int j = 0; j < 4; j++){
        const int ch = tid + 256*j;           // 0..1023
        const int row = ch >> 3, c = ch & 7;
        const uint32_t so = sb + (uint32_t)(row*AQ_ROW + c*16);
        const size_t g = qoff + (size_t)row*HS_ + c*8;
        cpa16(so,        g_Qh + g);
        cpa16(so + A_MQ, g_Ql + g);
    }

    auto load_kv = [&](int kt2, int s){
        const uint32_t st = sb + A_QTOT + (uint32_t)s * A_STG;
        const size_t koff = ((size_t)bh*T_ + kt2*64) * HS_;
        const size_t voff = (size_t)bh*HS_*T_ + kt2*64;
        #pragma unroll
        for (int j = 0; j < 2; j++){
            const int ch = tid + 256*j;       // 0..511
            const int row = ch >> 3, c = ch & 7;
            const uint32_t sk = st + (uint32_t)(row*AK_ROW + c*16);
            const size_t gk = koff + (size_t)row*HS_ + c*8;
            cpa16(sk + A_KH, g_Kh + gk);
            cpa16(sk + A_KL, g_Kl + gk);
            const uint32_t sv = st + (uint32_t)(row*AV_ROW + c*16);
            const size_t gv = voff + (size_t)row*T_ + c*8;
            cpa16(sv + A_VH, g_Vh + gv);
            cpa16(sv + A_VL, g_Vl + gv);
        }
        asm volatile("cp.async.commit_group;");
    };

    load_kv(0, 0);   // group 0 = Q + stage0

    float m0 = -1e30f, m1 = -1e30f, l0 = 0.f, l1 = 0.f;
    float o[8][4];
    #pragma unroll
    for (int j2 = 0; j2 < 8; j2++)
        #pragma unroll
        for (int q = 0; q < 4; q++) o[j2][q] = 0.f;

    const uint32_t offQ = lm_offA(lane, AQ_ROW) + (uint32_t)(w*16)*AQ_ROW;
    const uint32_t offK = lm_offB(lane, AK_ROW);
    const uint32_t offV = lm_offB(lane, AV_ROW);

    // Loop-invariant Q fragments (loaded once at kt2==0)
    uint32_t qh_r[4][4], ql_r[4][4];

    const int nkt = 2*(qt + 1);    // number of 64-wide k tiles

    for (int kt2 = 0; kt2 < nkt; kt2++){
        if (kt2 + 1 < nkt){
            load_kv(kt2 + 1, (kt2 + 1) & 1);
            asm volatile("cp.async.wait_group 1;");
        } else {
            asm volatile("cp.async.wait_group 0;");
        }
        __syncthreads();

        if (kt2 == 0){
            #pragma unroll
            for (int kk = 0; kk < 4; kk++){
                const uint32_t qa = sb + offQ + kk*32;
                ldsm4(qh_r[kk][0], qh_r[kk][1], qh_r[kk][2], qh_r[kk][3], qa);
                ldsm4(ql_r[kk][0], ql_r[kk][1], ql_r[kk][2], ql_r[kk][3],
                      qa + A_MQ);
            }
        }

        const uint32_t st = sb + A_QTOT + (uint32_t)(kt2 & 1) * A_STG;

        // ---- S = Q @ K^T (3-pass hi/lo), 64 k-rows ----
        float s[8][4];
        #pragma unroll
        for (int j = 0; j < 8; j++){
            s[j][0] = s[j][1] = s[j][2] = s[j][3] = 0.f;
        }
        #pragma unroll
        for (int kk = 0; kk < 4; kk++){           // d = 64 -> 4 k16 steps
            #pragma unroll
            for (int jq = 0; jq < 2; jq++){       // 32 k-rows per block
                const uint32_t ka = st + A_KH + offK
                                  + (uint32_t)(jq*32)*AK_ROW + kk*32;
                uint32_t kh[4][2], kl[4][2];
                ldsm4(kh[0][0], kh[0][1], kh[1][0], kh[1][1], ka);
                ldsm4(kh[2][0], kh[2][1], kh[3][0], kh[3][1],
                      ka + (uint32_t)16*AK_ROW);
                ldsm4(kl[0][0], kl[0][1], kl[1][0], kl[1][1], ka + A_MK);
                ldsm4(kl[2][0], kl[2][1], kl[3][0], kl[3][1],
                      ka + A_MK + (uint32_t)16*AK_ROW);
                float* s0 = s[4*jq + 0]; float* s1 = s[4*jq + 1];
                float* s2 = s[4*jq + 2]; float* s3 = s[4*jq + 3];
                mma16816(s0, qh_r[kk], kh[0]); mma16816(s1, qh_r[kk], kh[1]);
                mma16816(s2, qh_r[kk], kh[2]); mma16816(s3, qh_r[kk], kh[3]);
                mma16816(s0, qh_r[kk], kl[0]); mma16816(s1, qh_r[kk], kl[1]);
                mma16816(s2, qh_r[kk], kl[2]); mma16816(s3, qh_r[kk], kl[3]);
                mma16816(s0, ql_r[kk], kh[0]); mma16816(s1, ql_r[kk], kh[1]);
                mma16816(s2, ql_r[kk], kh[2]); mma16816(s3, ql_r[kk], kh[3]);
            }
        }

        // ---- causal mask (only the two diagonal-overlapping tiles) ----
        if (kt2 >= 2*qt){
            const int base = (kt2 - 2*qt)*64;     // 0 or 64
            const int row0 = w*16 + r;
            #pragma unroll
            for (int j = 0; j < 8; j++){
                const int col0 = base + j*8 + c4*2;
                if (col0     > row0    ) s[j][0] = -1e30f;
                if (col0 + 1 > row0    ) s[j][1] = -1e30f;
                if (col0     > row0 + 8) s[j][2] = -1e30f;
                if (col0 + 1 > row0 + 8) s[j][3] = -1e30f;
            }
        }

        // ---- online softmax ----
        float rm0 = -1e30f, rm1 = -1e30f;
        #pragma unroll
        for (int j = 0; j < 8; j++){
            rm0 = fmaxf(rm0, fmaxf(s[j][0], s[j][1]));
            rm1 = fmaxf(rm1, fmaxf(s[j][2], s[j][3]));
        }
        rm0 = fmaxf(rm0, __shfl_xor_sync(0xffffffffu, rm0, 1));
        rm0 = fmaxf(rm0, __shfl_xor_sync(0xffffffffu, rm0, 2));
        rm1 = fmaxf(rm1, __shfl_xor_sync(0xffffffffu, rm1, 1));
        rm1 = fmaxf(rm1, __shfl_xor_sync(0xffffffffu, rm1, 2));
        const float mn0 = fmaxf(m0, rm0), mn1 = fmaxf(m1, rm1);
        const float a0 = __expf(m0 - mn0), a1 = __expf(m1 - mn1);
        m0 = mn0; m1 = mn1;
        float rs0 = 0.f, rs1 = 0.f;
        #pragma unroll
        for (int j = 0; j < 8; j++){
            s[j][0] = __expf(s[j][0] - mn0);
            s[j][1] = __expf(s[j][1] - mn0);
            s[j][2] = __expf(s[j][2] - mn1);
            s[j][3] = __expf(s[j][3] - mn1);
            rs0 += s[j][0] + s[j][1];
            rs1 += s[j][2] + s[j][3];
        }
        rs0 += __shfl_xor_sync(0xffffffffu, rs0, 1);
        rs0 += __shfl_xor_sync(0xffffffffu, rs0, 2);
        rs1 += __shfl_xor_sync(0xffffffffu, rs1, 1);
        rs1 += __shfl_xor_sync(0xffffffffu, rs1, 2);
        l0 = l0*a0 + rs0;
        l1 = l1*a1 + rs1;
        #pragma unroll
        for (int j2 = 0; j2 < 8; j2++){
            o[j2][0] *= a0; o[j2][1] *= a0;
            o[j2][2] *= a1; o[j2][3] *= a1;
        }

        // ---- O += P @ V (3-pass: Ph*Vh + Ph*Vl + Pl*Vh) ----
        #pragma unroll
        for (int kk = 0; kk < 4; kk++){           // t = 64 -> 4 k16 steps
            float ph[8], pl[8];
            #pragma unroll
            for (int e = 0; e < 4; e++){
                ph[e]   = bfhi(s[2*kk  ][e]);  pl[e]   = s[2*kk  ][e] - ph[e];
                ph[4+e] = bfhi(s[2*kk+1][e]);  pl[4+e] = s[2*kk+1][e] - ph[4+e];
            }
            uint32_t a_h[4], a_l[4];
            a_h[0] = packbf(ph[0], ph[1]);  a_h[1] = packbf(ph[2], ph[3]);
            a_h[2] = packbf(ph[4], ph[5]);  a_h[3] = packbf(ph[6], ph[7]);
            a_l[0] = packbf(pl[0], pl[1]);  a_l[1] = packbf(pl[2], pl[3]);
            a_l[2] = packbf(pl[4], pl[5]);  a_l[3] = packbf(pl[6], pl[7]);
            #pragma unroll
            for (int jq = 0; jq < 2; jq++){       // 32 d-rows per block
                const uint32_t va = st + A_VH + offV
                                  + (uint32_t)(jq*32)*AV_ROW + kk*32;
                uint32_t vh[4][2], vl[4][2];
                ldsm4(vh[0][0], vh[0][1], vh[1][0], vh[1][1], va);
                ldsm4(vh[2][0], vh[2][1], vh[3][0], vh[3][1],
                      va + (uint32_t)16*AV_ROW);
                ldsm4(vl[0][0], vl[0][1], vl[1][0], vl[1][1], va + A_MV);
                ldsm4(vl[2][0], vl[2][1], vl[3][0], vl[3][1],
                      va + A_MV + (uint32_t)16*AV_ROW);
                float* o0 = o[4*jq + 0]; float* o1 = o[4*jq + 1];
                float* o2 = o[4*jq + 2]; float* o3 = o[4*jq + 3];
                mma16816(o0, a_h, vh[0]); mma16816(o1, a_h, vh[1]);
                mma16816(o2, a_h, vh[2]); mma16816(o3, a_h, vh[3]);
                mma16816(o0, a_h, vl[0]); mma16816(o1, a_h, vl[1]);
                mma16816(o2, a_h, vl[2]); mma16816(o3, a_h, vl[3]);
                mma16816(o0, a_l, vh[0]); mma16816(o1, a_l, vh[1]);
                mma16816(o2, a_l, vh[2]); mma16816(o3, a_l, vh[3]);
            }
        }
        __syncthreads();
    }

    // ---- epilogue: write YH/YL bf16 hi/lo [M][768] ----
    const float inv0 = 1.f / l0, inv1 = 1.f / l1;
    const int bq = bh / H_, hh = bh % H_;
    const int t0 = qt*128 + w*16 + r;
    #pragma unroll
    for (int j2 = 0; j2 < 8; j2++){
        const int cc = hh*64 + j2*8 + c4*2;
        const float y0 = o[j2][0]*inv0, y1 = o[j2][1]*inv0;
        const float y2 = o[j2][2]*inv1, y3 = o[j2][3]*inv1;
        const size_t r0 = (size_t)(bq*T_ + t0    )*C_ + cc;
        const size_t r1 = (size_t)(bq*T_ + t0 + 8)*C_ + cc;
        *(uint32_t*)&g_YH[r0] = packbf(y0, y1);
        *(uint32_t*)&g_YL[r0] = packbf(y0 - bfhi(y0), y1 - bfhi(y1));
        *(uint32_t*)&g_YH[r1] = packbf(y2, y3);
        *(uint32_t*)&g_YL[r1] = packbf(y2 - bfhi(y2), y3 - bfhi(y3));
    }
}

// ---------------------------------------------------------------------------
extern "C" void kernel_launch(void* const* d_in, const int* in_sizes, int n_in,
                              void* d_out, int out_size)
{
    const float* x      = (const float*)d_in[0];
    const float* w_attn = (const float*)d_in[1];
    const float* b_attn = (const float*)d_in[2];
    const float* w_proj = (const float*)d_in[3];
    const float* b_proj = (const float*)d_in[4];
    float* out = (float*)d_out;

    cudaFuncSetAttribute(mma_gemm<1>, cudaFuncAttributeMaxDynamicSharedMemorySize, GEMM_SMEM);
    cudaFuncSetAttribute(mma_gemm<0>, cudaFuncAttributeMaxDynamicSharedMemorySize, GEMM_SMEM);
    cudaFuncSetAttribute(attn_tc, cudaFuncAttributeMaxDynamicSharedMemorySize, ATTN_SMEM);

    convert_split_x<<<(M_*C_/4 + 255)/256, 256>>>(x);
    transpose_split<0><<<dim3(3*C_/32, C_/32), dim3(32, 8)>>>(w_attn);
    transpose_split<1><<<dim3(C_/32,   C_/32), dim3(32, 8)>>>(w_proj);

    mma_gemm<1><<<dim3(3*C_/128, M_/128), 256, GEMM_SMEM>>>(b_attn, nullptr);
    attn_tc<<<dim3(T_/128, B_*H_), 256, ATTN_SMEM>>>();
    mma_gemm<0><<<dim3(C_/128, M_/128), 256, GEMM_SMEM>>>(b_proj, out);
}

// round 12
// speedup vs baseline: 1.4831x; 1.3768x over previous
#include <cuda_runtime.h>
#include <cuda_fp16.h>
#include <cstdint>

// Problem constants
#define B_  8
#define T_  1024
#define C_  768
#define H_  12
#define HS_ 64
#define M_  8192   // B*T

// ---------------------------------------------------------------------------
// Device-global scratch (no runtime allocation allowed)
// X/Y: fp16 hi/lo pairs. Weights: SINGLE fp16 (transposed, K-major).
// Q: fp16 hi/lo (prescaled 0.125). K: single fp16. V: single fp16 [B,H,hs,T].
// ---------------------------------------------------------------------------
__device__ __half g_XH[(size_t)M_*C_], g_XL[(size_t)M_*C_];
__device__ __half g_YH[(size_t)M_*C_], g_YL[(size_t)M_*C_];
__device__ __half g_Wa[(size_t)3*C_*C_];
__device__ __half g_Wp[(size_t)C_*C_];

__device__ __half g_Qh[B_*H_*T_*HS_], g_Ql[B_*H_*T_*HS_];
__device__ __half g_K [B_*H_*T_*HS_];
__device__ __half g_V [B_*H_*T_*HS_];

// ---------------------------------------------------------------------------
// Helpers (portable PTX only — compiles for plain sm_103 target)
// ---------------------------------------------------------------------------
__device__ __forceinline__ uint32_t smem_u32(const void* p){
    return (uint32_t)__cvta_generic_to_shared(p);
}
__device__ __forceinline__ void cpa16(uint32_t d, const void* s){
    asm volatile("cp.async.cg.shared.global [%0], [%1], 16;" :: "r"(d), "l"(s));
}
__device__ __forceinline__ void ldsm4(uint32_t& r0, uint32_t& r1,
                                      uint32_t& r2, uint32_t& r3, uint32_t a){
    asm volatile("ldmatrix.sync.aligned.m8n8.x4.shared.b16 {%0,%1,%2,%3}, [%4];"
                 : "=r"(r0), "=r"(r1), "=r"(r2), "=r"(r3) : "r"(a));
}
__device__ __forceinline__ void mma16816(float acc[4], const uint32_t a[4],
                                         const uint32_t b[2]){
    asm volatile(
        "mma.sync.aligned.m16n8k16.row.col.f32.f16.f16.f32 "
        "{%0,%1,%2,%3}, {%4,%5,%6,%7}, {%8,%9}, {%0,%1,%2,%3};"
        : "+f"(acc[0]), "+f"(acc[1]), "+f"(acc[2]), "+f"(acc[3])
        : "r"(a[0]), "r"(a[1]), "r"(a[2]), "r"(a[3]), "r"(b[0]), "r"(b[1]));
}
__device__ __forceinline__ uint32_t packhf(float x, float y){
    __half2 t = __float22half2_rn(make_float2(x, y));
    return *(uint32_t*)&t;
}
__device__ __forceinline__ float hfhi(float x){
    return __half2float(__float2half_rn(x));
}

// per-lane ldmatrix row-offset helpers (byte offsets within a tile):
__device__ __forceinline__ uint32_t lm_offA(int lane, int rowb){
    return (uint32_t)(((lane & 7) + ((lane >> 3) & 1)*8) * rowb + (lane >> 4)*16);
}
__device__ __forceinline__ uint32_t lm_offB(int lane, int rowb){
    return (uint32_t)(((lane & 7) + (lane >> 4)*8) * rowb + ((lane >> 3) & 1)*16);
}

// ---------------------------------------------------------------------------
// Pre-pass: split x fp32 -> fp16 hi/lo
// ---------------------------------------------------------------------------
__global__ void convert_split_x(const float* __restrict__ src)
{
    const int i = blockIdx.x * blockDim.x + threadIdx.x;   // float4 index
    const int n4 = (M_*C_) / 4;
    if (i >= n4) return;
    const float4 v = ((const float4*)src)[i];
    const float h0 = hfhi(v.x), h1 = hfhi(v.y), h2 = hfhi(v.z), h3 = hfhi(v.w);
    ((uint32_t*)g_XH)[i*2    ] = packhf(v.x, v.y);
    ((uint32_t*)g_XH)[i*2 + 1] = packhf(v.z, v.w);
    ((uint32_t*)g_XL)[i*2    ] = packhf(v.x - h0, v.y - h1);
    ((uint32_t*)g_XL)[i*2 + 1] = packhf(v.z - h2, v.w - h3);
}

// ---------------------------------------------------------------------------
// Pre-pass: transpose weights -> [N][768] SINGLE fp16 (K-major)
// ---------------------------------------------------------------------------
template<int WHICH>
__global__ void transpose_w(const float* __restrict__ w)
{
    constexpr int N = (WHICH == 0) ? 3*C_ : C_;
    __half* Hh = (WHICH == 0) ? g_Wa : g_Wp;

    __shared__ float tile[32][33];
    const int nb = blockIdx.x * 32;
    const int kb = blockIdx.y * 32;
    const int tx = threadIdx.x;
    const int ty = threadIdx.y;

    #pragma unroll
    for (int i = ty; i < 32; i += 8)
        tile[i][tx] = w[(size_t)(kb + i) * N + nb + tx];
    __syncthreads();

    #pragma unroll
    for (int i = ty; i < 32; i += 8){
        const float v = tile[tx][i];
        Hh[(size_t)(nb + i) * C_ + kb + tx] = __float2half_rn(v);
    }
}

// ---------------------------------------------------------------------------
// Tensor-core GEMM, fp16 2-pass: C = (Ah + Al) @ W^T, W single fp16.
// 128x128 CTA tile, 8 warps (2m x 4n), occ 2, ldmatrix loads.
// MODE 1: A=XH/XL, B=Wa -> Qh/Ql (scaled), K single, V single transposed
// MODE 0: A=YH/YL, B=Wp -> fp32 Cout (d_out)
// ---------------------------------------------------------------------------
constexpr int ROWB   = 80;
constexpr int MATB   = 128 * ROWB;   // 10240
constexpr int ST_B   = 2 * MATB;     // B region offset
constexpr int STAGEB = 3 * MATB;     // 30720 (AH, AL, B)
constexpr int GEMM_SMEM = 2 * STAGEB;// 61440

template<int MODE>
__global__ __launch_bounds__(256, 2)
void mma_gemm(const float* __restrict__ bias, float* __restrict__ Cout)
{
    extern __shared__ __align__(128) uint8_t smem[];

    const __half* AH = (MODE == 1) ? g_XH : g_YH;
    const __half* AL = (MODE == 1) ? g_XL : g_YL;
    const __half* Bm = (MODE == 1) ? g_Wa : g_Wp;

    const int tid  = threadIdx.x;
    const int lane = tid & 31;
    const int warp = tid >> 5;
    const int wm   = warp & 1;
    const int wn   = warp >> 1;
    const int bc   = blockIdx.x;
    const int br   = blockIdx.y;

    const uint32_t sb = smem_u32(smem);

    auto load_stage = [&](int kt, int s){
        const uint32_t st = sb + (uint32_t)s * STAGEB;
        #pragma unroll
        for (int j = 0; j < 2; j++){
            const int ch  = tid + j*256;
            const int row = ch >> 2;
            const int cc  = ch & 3;
            const uint32_t so = (uint32_t)(row*ROWB + cc*16);
            const size_t ga = (size_t)(br*128 + row) * C_ + kt*32 + cc*8;
            const size_t gb = (size_t)(bc*128 + row) * C_ + kt*32 + cc*8;
            cpa16(st          + so, AH + ga);
            cpa16(st +  MATB  + so, AL + ga);
            cpa16(st +  ST_B  + so, Bm + gb);
        }
        asm volatile("cp.async.commit_group;");
    };

    float acc[4][4][4];
    #pragma unroll
    for (int i = 0; i < 4; i++)
        #pragma unroll
        for (int j = 0; j < 4; j++)
            #pragma unroll
            for (int q = 0; q < 4; q++) acc[i][j][q] = 0.f;

    constexpr int NK = C_ / 32;    // 24

    load_stage(0, 0);
    asm volatile("cp.async.wait_group 0;");
    __syncthreads();

    const uint32_t offA = lm_offA(lane, ROWB) + (uint32_t)(wm*64)*ROWB;
    const uint32_t offB = lm_offB(lane, ROWB) + (uint32_t)(wn*32)*ROWB + ST_B;

    for (int kt = 0; kt < NK; kt++){
        const int cur = kt & 1;
        if (kt + 1 < NK) load_stage(kt + 1, cur ^ 1);

        const uint32_t st = sb + (uint32_t)cur * STAGEB;

        #pragma unroll
        for (int kk = 0; kk < 2; kk++){
            uint32_t bf[4][2];
            #pragma unroll
            for (int jp = 0; jp < 2; jp++){
                const uint32_t ab = st + offB + (uint32_t)(jp*16)*ROWB + kk*32;
                ldsm4(bf[2*jp][0], bf[2*jp][1], bf[2*jp+1][0], bf[2*jp+1][1], ab);
            }
            #pragma unroll
            for (int i = 0; i < 4; i++){
                const uint32_t aa = st + offA + (uint32_t)(i*16)*ROWB + kk*32;
                uint32_t ah[4], al[4];
                ldsm4(ah[0], ah[1], ah[2], ah[3], aa);
                ldsm4(al[0], al[1], al[2], al[3], aa + MATB);
                #pragma unroll
                for (int j = 0; j < 4; j++) mma16816(acc[i][j], ah, bf[j]);
                #pragma unroll
                for (int j = 0; j < 4; j++) mma16816(acc[i][j], al, bf[j]);
            }
        }

        if (kt + 1 < NK) asm volatile("cp.async.wait_group 0;");
        __syncthreads();
    }

    const int r  = lane >> 2;
    const int c4 = lane & 3;

    // Epilogue
    #pragma unroll
    for (int j = 0; j < 4; j++){
        const int col = bc*128 + wn*32 + j*8 + c4*2;
        const float2 bv = *(const float2*)&bias[col];
        if (MODE == 0){
            #pragma unroll
            for (int i = 0; i < 4; i++){
                const int row0 = br*128 + wm*64 + i*16 + r;
                float2 v0 = make_float2(acc[i][j][0] + bv.x, acc[i][j][1] + bv.y);
                float2 v1 = make_float2(acc[i][j][2] + bv.x, acc[i][j][3] + bv.y);
                *(float2*)&Cout[(size_t)row0     * C_ + col] = v0;
                *(float2*)&Cout[(size_t)(row0+8) * C_ + col] = v1;
            }
        } else {
            const int which = col / C_;
            const int rem   = col - which * C_;
            const int hh = rem >> 6;
            const int dd = rem & 63;
            #pragma unroll
            for (int i = 0; i < 4; i++){
                const int row0 = br*128 + wm*64 + i*16 + r;
                const int b0i = row0 >> 10, t0i = row0 & 1023;
                const int row1 = row0 + 8;
                const int b1i = row1 >> 10, t1i = row1 & 1023;
                float v00 = acc[i][j][0] + bv.x, v01 = acc[i][j][1] + bv.y;
                float v10 = acc[i][j][2] + bv.x, v11 = acc[i][j][3] + bv.y;
                if (which == 0){ v00*=0.125f; v01*=0.125f; v10*=0.125f; v11*=0.125f; }
                const size_t o0 = ((size_t)(b0i*H_ + hh)*T_ + t0i)*HS_ + dd;
                const size_t o1 = ((size_t)(b1i*H_ + hh)*T_ + t1i)*HS_ + dd;
                if (which == 0){
                    *(uint32_t*)&g_Qh[o0] = packhf(v00, v01);
                    *(uint32_t*)&g_Ql[o0] = packhf(v00 - hfhi(v00), v01 - hfhi(v01));
                    *(uint32_t*)&g_Qh[o1] = packhf(v10, v11);
                    *(uint32_t*)&g_Ql[o1] = packhf(v10 - hfhi(v10), v11 - hfhi(v11));
                } else if (which == 1){
                    *(uint32_t*)&g_K[o0] = packhf(v00, v01);
                    *(uint32_t*)&g_K[o1] = packhf(v10, v11);
                } else {
                    // V transposed: [B,H,d,T], single fp16
                    const size_t vb0 = ((size_t)(b0i*H_ + hh)*HS_ + dd)*T_;
                    const size_t vb1 = ((size_t)(b1i*H_ + hh)*HS_ + dd)*T_;
                    g_V[vb0      + t0i] = __float2half_rn(v00);
                    g_V[vb0 + T_ + t0i] = __float2half_rn(v01);
                    g_V[vb1      + t1i] = __float2half_rn(v10);
                    g_V[vb1 + T_ + t1i] = __float2half_rn(v11);
                }
            }
        }
    }
}

// ---------------------------------------------------------------------------
// Tensor-core causal flash attention, fp16 2-pass:
// S = (Qh+Ql)@K^T (K single); O += (Ph+Pl)@V (V single).
// q-tile 128, k-tiles 64, occ 2, Q fragments register-cached.
// smem: Q hi/lo 2x18432 + 2 stages x (K 9216 + V 9216) = 73728 B.
// ---------------------------------------------------------------------------
constexpr int AQ_ROW = 144;
constexpr int AK_ROW = 144;
constexpr int AV_ROW = 144;
constexpr int A_MQ   = 128 * AQ_ROW;     // 18432
constexpr int A_MK   = 64  * AK_ROW;     // 9216
constexpr int A_MV   = 64  * AV_ROW;     // 9216
constexpr int A_QTOT = 2 * A_MQ;         // 36864
constexpr int A_VOFF = A_MK;             // V offset within stage
constexpr int A_STG  = A_MK + A_MV;      // 18432
constexpr int ATTN_SMEM = A_QTOT + 2*A_STG;  // 73728

__global__ __launch_bounds__(256, 2)
void attn_tc()
{
    extern __shared__ __align__(128) uint8_t smx[];
    const uint32_t sb = smem_u32(smx);

    const int qt  = blockIdx.x;    // 0..7 (128-row q tiles)
    const int bh  = blockIdx.y;    // 0..95
    const int tid = threadIdx.x;
    const int lane = tid & 31;
    const int w    = tid >> 5;
    const int r    = lane >> 2;
    const int c4   = lane & 3;

    // ---- Q load (hi/lo), 128 rows ----
    const size_t qoff = ((size_t)bh*T_ + qt*128) * HS_;
    #pragma unroll
    for (int j = 0; j < 4; j++){
        const int ch = tid + 256*j;           // 0..1023
        const int row = ch >> 3, c = ch & 7;
        const uint32_t so = sb + (uint32_t)(row*AQ_ROW + c*16);
        const size_t g = qoff + (size_t)row*HS_ + c*8;
        cpa16(so,        g_Qh + g);
        cpa16(so + A_MQ, g_Ql + g);
    }

    auto load_kv = [&](int kt2, int s){
        const uint32_t st = sb + A_QTOT + (uint32_t)s * A_STG;
        const size_t koff = ((size_t)bh*T_ + kt2*64) * HS_;
        const size_t voff = (size_t)bh*HS_*T_ + kt2*64;
        #pragma unroll
        for (int j = 0; j < 2; j++){
            const int ch = tid + 256*j;       // 0..511
            const int row = ch >> 3, c = ch & 7;
            const uint32_t sk = st + (uint32_t)(row*AK_ROW + c*16);
            cpa16(sk, g_K + koff + (size_t)row*HS_ + c*8);
            const uint32_t sv = st + A_VOFF + (uint32_t)(row*AV_ROW + c*16);
            cpa16(sv, g_V + voff + (size_t)row*T_ + c*8);
        }
        asm volatile("cp.async.commit_group;");
    };

    load_kv(0, 0);   // group 0 = Q + stage0

    float m0 = -1e30f, m1 = -1e30f, l0 = 0.f, l1 = 0.f;
    float o[8][4];
    #pragma unroll
    for (int j2 = 0; j2 < 8; j2++)
        #pragma unroll
        for (int q = 0; q < 4; q++) o[j2][q] = 0.f;

    const uint32_t offQ = lm_offA(lane, AQ_ROW) + (uint32_t)(w*16)*AQ_ROW;
    const uint32_t offK = lm_offB(lane, AK_ROW);
    const uint32_t offV = lm_offB(lane, AV_ROW);

    // Loop-invariant Q fragments (loaded once at kt2==0)
    uint32_t qh_r[4][4], ql_r[4][4];

    const int nkt = 2*(qt + 1);

    for (int kt2 = 0; kt2 < nkt; kt2++){
        if (kt2 + 1 < nkt){
            load_kv(kt2 + 1, (kt2 + 1) & 1);
            asm volatile("cp.async.wait_group 1;");
        } else {
            asm volatile("cp.async.wait_group 0;");
        }
        __syncthreads();

        if (kt2 == 0){
            #pragma unroll
            for (int kk = 0; kk < 4; kk++){
                const uint32_t qa = sb + offQ + kk*32;
                ldsm4(qh_r[kk][0], qh_r[kk][1], qh_r[kk][2], qh_r[kk][3], qa);
                ldsm4(ql_r[kk][0], ql_r[kk][1], ql_r[kk][2], ql_r[kk][3],
                      qa + A_MQ);
            }
        }

        const uint32_t st = sb + A_QTOT + (uint32_t)(kt2 & 1) * A_STG;

        // ---- S = (Qh+Ql) @ K^T (2-pass), 64 k-rows ----
        float s[8][4];
        #pragma unroll
        for (int j = 0; j < 8; j++){
            s[j][0] = s[j][1] = s[j][2] = s[j][3] = 0.f;
        }
        #pragma unroll
        for (int kk = 0; kk < 4; kk++){           // d = 64 -> 4 k16 steps
            #pragma unroll
            for (int jq = 0; jq < 2; jq++){       // 32 k-rows per block
                const uint32_t ka = st + offK
                                  + (uint32_t)(jq*32)*AK_ROW + kk*32;
                uint32_t kh[4][2];
                ldsm4(kh[0][0], kh[0][1], kh[1][0], kh[1][1], ka);
                ldsm4(kh[2][0], kh[2][1], kh[3][0], kh[3][1],
                      ka + (uint32_t)16*AK_ROW);
                float* s0 = s[4*jq + 0]; float* s1 = s[4*jq + 1];
                float* s2 = s[4*jq + 2]; float* s3 = s[4*jq + 3];
                mma16816(s0, qh_r[kk], kh[0]); mma16816(s1, qh_r[kk], kh[1]);
                mma16816(s2, qh_r[kk], kh[2]); mma16816(s3, qh_r[kk], kh[3]);
                mma16816(s0, ql_r[kk], kh[0]); mma16816(s1, ql_r[kk], kh[1]);
                mma16816(s2, ql_r[kk], kh[2]); mma16816(s3, ql_r[kk], kh[3]);
            }
        }

        // ---- causal mask (only the two diagonal-overlapping tiles) ----
        if (kt2 >= 2*qt){
            const int base = (kt2 - 2*qt)*64;     // 0 or 64
            const int row0 = w*16 + r;
            #pragma unroll
            for (int j = 0; j < 8; j++){
                const int col0 = base + j*8 + c4*2;
                if (col0     > row0    ) s[j][0] = -1e30f;
                if (col0 + 1 > row0    ) s[j][1] = -1e30f;
                if (col0     > row0 + 8) s[j][2] = -1e30f;
                if (col0 + 1 > row0 + 8) s[j][3] = -1e30f;
            }
        }

        // ---- online softmax ----
        float rm0 = -1e30f, rm1 = -1e30f;
        #pragma unroll
        for (int j = 0; j < 8; j++){
            rm0 = fmaxf(rm0, fmaxf(s[j][0], s[j][1]));
            rm1 = fmaxf(rm1, fmaxf(s[j][2], s[j][3]));
        }
        rm0 = fmaxf(rm0, __shfl_xor_sync(0xffffffffu, rm0, 1));
        rm0 = fmaxf(rm0, __shfl_xor_sync(0xffffffffu, rm0, 2));
        rm1 = fmaxf(rm1, __shfl_xor_sync(0xffffffffu, rm1, 1));
        rm1 = fmaxf(rm1, __shfl_xor_sync(0xffffffffu, rm1, 2));
        const float mn0 = fmaxf(m0, rm0), mn1 = fmaxf(m1, rm1);
        const float a0 = __expf(m0 - mn0), a1 = __expf(m1 - mn1);
        m0 = mn0; m1 = mn1;
        float rs0 = 0.f, rs1 = 0.f;
        #pragma unroll
        for (int j = 0; j < 8; j++){
            s[j][0] = __expf(s[j][0] - mn0);
            s[j][1] = __expf(s[j][1] - mn0);
            s[j][2] = __expf(s[j][2] - mn1);
            s[j][3] = __expf(s[j][3] - mn1);
            rs0 += s[j][0] + s[j][1];
            rs1 += s[j][2] + s[j][3];
        }
        rs0 += __shfl_xor_sync(0xffffffffu, rs0, 1);
        rs0 += __shfl_xor_sync(0xffffffffu, rs0, 2);
        rs1 += __shfl_xor_sync(0xffffffffu, rs1, 1);
        rs1 += __shfl_xor_sync(0xffffffffu, rs1, 2);
        l0 = l0*a0 + rs0;
        l1 = l1*a1 + rs1;
        #pragma unroll
        for (int j2 = 0; j2 < 8; j2++){
            o[j2][0] *= a0; o[j2][1] *= a0;
            o[j2][2] *= a1; o[j2][3] *= a1;
        }

        // ---- O += (Ph+Pl) @ V (2-pass, V single) ----
        #pragma unroll
        for (int kk = 0; kk < 4; kk++){           // t = 64 -> 4 k16 steps
            float ph[8], pl[8];
            #pragma unroll
            for (int e = 0; e < 4; e++){
                ph[e]   = hfhi(s[2*kk  ][e]);  pl[e]   = s[2*kk  ][e] - ph[e];
                ph[4+e] = hfhi(s[2*kk+1][e]);  pl[4+e] = s[2*kk+1][e] - ph[4+e];
            }
            uint32_t a_h[4], a_l[4];
            a_h[0] = packhf(ph[0], ph[1]);  a_h[1] = packhf(ph[2], ph[3]);
            a_h[2] = packhf(ph[4], ph[5]);  a_h[3] = packhf(ph[6], ph[7]);
            a_l[0] = packhf(pl[0], pl[1]);  a_l[1] = packhf(pl[2], pl[3]);
            a_l[2] = packhf(pl[4], pl[5]);  a_l[3] = packhf(pl[6], pl[7]);
            #pragma unroll
            for (int jq = 0; jq < 2; jq++){       // 32 d-rows per block
                const uint32_t va = st + A_VOFF + offV
                                  + (uint32_t)(jq*32)*AV_ROW + kk*32;
                uint32_t vh[4][2];
                ldsm4(vh[0][0], vh[0][1], vh[1][0], vh[1][1], va);
                ldsm4(vh[2][0], vh[2][1], vh[3][0], vh[3][1],
                      va + (uint32_t)16*AV_ROW);
                float* o0 = o[4*jq + 0]; float* o1 = o[4*jq + 1];
                float* o2 = o[4*jq + 2]; float* o3 = o[4*jq + 3];
                mma16816(o0, a_h, vh[0]); mma16816(o1, a_h, vh[1]);
                mma16816(o2, a_h, vh[2]); mma16816(o3, a_h, vh[3]);
                mma16816(o0, a_l, vh[0]); mma16816(o1, a_l, vh[1]);
                mma16816(o2, a_l, vh[2]); mma16816(o3, a_l, vh[3]);
            }
        }
        __syncthreads();
    }

    // ---- epilogue: write YH/YL fp16 hi/lo [M][768] ----
    const float inv0 = 1.f / l0, inv1 = 1.f / l1;
    const int bq = bh / H_, hh = bh % H_;
    const int t0 = qt*128 + w*16 + r;
    #pragma unroll
    for (int j2 = 0; j2 < 8; j2++){
        const int cc = hh*64 + j2*8 + c4*2;
        const float y0 = o[j2][0]*inv0, y1 = o[j2][1]*inv0;
        const float y2 = o[j2][2]*inv1, y3 = o[j2][3]*inv1;
        const size_t r0 = (size_t)(bq*T_ + t0    )*C_ + cc;
        const size_t r1 = (size_t)(bq*T_ + t0 + 8)*C_ + cc;
        *(uint32_t*)&g_YH[r0] = packhf(y0, y1);
        *(uint32_t*)&g_YL[r0] = packhf(y0 - hfhi(y0), y1 - hfhi(y1));
        *(uint32_t*)&g_YH[r1] = packhf(y2, y3);
        *(uint32_t*)&g_YL[r1] = packhf(y2 - hfhi(y2), y3 - hfhi(y3));
    }
}

// ---------------------------------------------------------------------------
extern "C" void kernel_launch(void* const* d_in, const int* in_sizes, int n_in,
                              void* d_out, int out_size)
{
    const float* x      = (const float*)d_in[0];
    const float* w_attn = (const float*)d_in[1];
    const float* b_attn = (const float*)d_in[2];
    const float* w_proj = (const float*)d_in[3];
    const float* b_proj = (const float*)d_in[4];
    float* out = (float*)d_out;

    cudaFuncSetAttribute(mma_gemm<1>, cudaFuncAttributeMaxDynamicSharedMemorySize, GEMM_SMEM);
    cudaFuncSetAttribute(mma_gemm<0>, cudaFuncAttributeMaxDynamicSharedMemorySize, GEMM_SMEM);
    cudaFuncSetAttribute(attn_tc, cudaFuncAttributeMaxDynamicSharedMemorySize, ATTN_SMEM);

    convert_split_x<<<(M_*C_/4 + 255)/256, 256>>>(x);
    transpose_w<0><<<dim3(3*C_/32, C_/32), dim3(32, 8)>>>(w_attn);
    transpose_w<1><<<dim3(C_/32,   C_/32), dim3(32, 8)>>>(w_proj);

    mma_gemm<1><<<dim3(3*C_/128, M_/128), 256, GEMM_SMEM>>>(b_attn, nullptr);
    attn_tc<<<dim3(T_/128, B_*H_), 256, ATTN_SMEM>>>();
    mma_gemm<0><<<dim3(C_/128, M_/128), 256, GEMM_SMEM>>>(b_proj, out);
}

// round 13
// speedup vs baseline: 2.0808x; 1.4030x over previous
#include <cuda_runtime.h>
#include <cuda_fp16.h>
#include <cstdint>

// Problem constants
#define B_  8
#define T_  1024
#define C_  768
#define H_  12
#define HS_ 64
#define M_  8192   // B*T

// ---------------------------------------------------------------------------
// Device-global scratch (no runtime allocation allowed)
// X: SINGLE fp16. Y: SINGLE fp16. Weights: single fp16 (transposed, K-major).
// Q: fp16 hi/lo (prescaled 0.125). K: single fp16. V: single fp16 [B,H,hs,T].
// ---------------------------------------------------------------------------
__device__ __half g_X [(size_t)M_*C_];
__device__ __half g_Y [(size_t)M_*C_];
__device__ __half g_Wa[(size_t)3*C_*C_];
__device__ __half g_Wp[(size_t)C_*C_];

__device__ __half g_Qh[B_*H_*T_*HS_], g_Ql[B_*H_*T_*HS_];
__device__ __half g_K [B_*H_*T_*HS_];
__device__ __half g_V [B_*H_*T_*HS_];

// ---------------------------------------------------------------------------
// Helpers (portable PTX only — compiles for plain sm_103 target)
// ---------------------------------------------------------------------------
__device__ __forceinline__ uint32_t smem_u32(const void* p){
    return (uint32_t)__cvta_generic_to_shared(p);
}
__device__ __forceinline__ void cpa16(uint32_t d, const void* s){
    asm volatile("cp.async.cg.shared.global [%0], [%1], 16;" :: "r"(d), "l"(s));
}
__device__ __forceinline__ void ldsm4(uint32_t& r0, uint32_t& r1,
                                      uint32_t& r2, uint32_t& r3, uint32_t a){
    asm volatile("ldmatrix.sync.aligned.m8n8.x4.shared.b16 {%0,%1,%2,%3}, [%4];"
                 : "=r"(r0), "=r"(r1), "=r"(r2), "=r"(r3) : "r"(a));
}
__device__ __forceinline__ void mma16816(float acc[4], const uint32_t a[4],
                                         const uint32_t b[2]){
    asm volatile(
        "mma.sync.aligned.m16n8k16.row.col.f32.f16.f16.f32 "
        "{%0,%1,%2,%3}, {%4,%5,%6,%7}, {%8,%9}, {%0,%1,%2,%3};"
        : "+f"(acc[0]), "+f"(acc[1]), "+f"(acc[2]), "+f"(acc[3])
        : "r"(a[0]), "r"(a[1]), "r"(a[2]), "r"(a[3]), "r"(b[0]), "r"(b[1]));
}
__device__ __forceinline__ uint32_t packhf(float x, float y){
    __half2 t = __float22half2_rn(make_float2(x, y));
    return *(uint32_t*)&t;
}
__device__ __forceinline__ float hfhi(float x){
    return __half2float(__float2half_rn(x));
}

// per-lane ldmatrix row-offset helpers (byte offsets within a tile):
__device__ __forceinline__ uint32_t lm_offA(int lane, int rowb){
    return (uint32_t)(((lane & 7) + ((lane >> 3) & 1)*8) * rowb + (lane >> 4)*16);
}
__device__ __forceinline__ uint32_t lm_offB(int lane, int rowb){
    return (uint32_t)(((lane & 7) + (lane >> 4)*8) * rowb + ((lane >> 3) & 1)*16);
}

// ---------------------------------------------------------------------------
// Pre-pass: convert x fp32 -> single fp16
// ---------------------------------------------------------------------------
__global__ void convert_x(const float* __restrict__ src)
{
    const int i = blockIdx.x * blockDim.x + threadIdx.x;   // float4 index
    const int n4 = (M_*C_) / 4;
    if (i >= n4) return;
    const float4 v = ((const float4*)src)[i];
    ((uint32_t*)g_X)[i*2    ] = packhf(v.x, v.y);
    ((uint32_t*)g_X)[i*2 + 1] = packhf(v.z, v.w);
}

// ---------------------------------------------------------------------------
// Pre-pass: transpose weights -> [N][768] SINGLE fp16 (K-major)
// ---------------------------------------------------------------------------
template<int WHICH>
__global__ void transpose_w(const float* __restrict__ w)
{
    constexpr int N = (WHICH == 0) ? 3*C_ : C_;
    __half* Hh = (WHICH == 0) ? g_Wa : g_Wp;

    __shared__ float tile[32][33];
    const int nb = blockIdx.x * 32;
    const int kb = blockIdx.y * 32;
    const int tx = threadIdx.x;
    const int ty = threadIdx.y;

    #pragma unroll
    for (int i = ty; i < 32; i += 8)
        tile[i][tx] = w[(size_t)(kb + i) * N + nb + tx];
    __syncthreads();

    #pragma unroll
    for (int i = ty; i < 32; i += 8){
        const float v = tile[tx][i];
        Hh[(size_t)(nb + i) * C_ + kb + tx] = __float2half_rn(v);
    }
}

// ---------------------------------------------------------------------------
// Tensor-core GEMM, pure fp16 1-pass: C = A @ W^T (A, W single fp16).
// 128x128 CTA tile, 8 warps (2m x 4n), occ 2, ldmatrix loads.
// MODE 1: A=X, B=Wa -> Qh/Ql (scaled), K single, V single transposed
// MODE 0: A=Y, B=Wp -> fp32 Cout (d_out)
// ---------------------------------------------------------------------------
constexpr int ROWB   = 80;
constexpr int MATB   = 128 * ROWB;   // 10240
constexpr int STAGEB = 2 * MATB;     // 20480 (A, B)
constexpr int GEMM_SMEM = 2 * STAGEB;// 40960

template<int MODE>
__global__ __launch_bounds__(256, 2)
void mma_gemm(const float* __restrict__ bias, float* __restrict__ Cout)
{
    extern __shared__ __align__(128) uint8_t smem[];

    const __half* Am = (MODE == 1) ? g_X  : g_Y;
    const __half* Bm = (MODE == 1) ? g_Wa : g_Wp;

    const int tid  = threadIdx.x;
    const int lane = tid & 31;
    const int warp = tid >> 5;
    const int wm   = warp & 1;
    const int wn   = warp >> 1;
    const int bc   = blockIdx.x;
    const int br   = blockIdx.y;

    const uint32_t sb = smem_u32(smem);

    auto load_stage = [&](int kt, int s){
        const uint32_t st = sb + (uint32_t)s * STAGEB;
        #pragma unroll
        for (int j = 0; j < 2; j++){
            const int ch  = tid + j*256;
            const int row = ch >> 2;
            const int cc  = ch & 3;
            const uint32_t so = (uint32_t)(row*ROWB + cc*16);
            const size_t ga = (size_t)(br*128 + row) * C_ + kt*32 + cc*8;
            const size_t gb = (size_t)(bc*128 + row) * C_ + kt*32 + cc*8;
            cpa16(st        + so, Am + ga);
            cpa16(st + MATB + so, Bm + gb);
        }
        asm volatile("cp.async.commit_group;");
    };

    float acc[4][4][4];
    #pragma unroll
    for (int i = 0; i < 4; i++)
        #pragma unroll
        for (int j = 0; j < 4; j++)
            #pragma unroll
            for (int q = 0; q < 4; q++) acc[i][j][q] = 0.f;

    constexpr int NK = C_ / 32;    // 24

    load_stage(0, 0);
    asm volatile("cp.async.wait_group 0;");
    __syncthreads();

    const uint32_t offA = lm_offA(lane, ROWB) + (uint32_t)(wm*64)*ROWB;
    const uint32_t offB = lm_offB(lane, ROWB) + (uint32_t)(wn*32)*ROWB + MATB;

    for (int kt = 0; kt < NK; kt++){
        const int cur = kt & 1;
        if (kt + 1 < NK) load_stage(kt + 1, cur ^ 1);

        const uint32_t st = sb + (uint32_t)cur * STAGEB;

        #pragma unroll
        for (int kk = 0; kk < 2; kk++){
            uint32_t bf[4][2];
            #pragma unroll
            for (int jp = 0; jp < 2; jp++){
                const uint32_t ab = st + offB + (uint32_t)(jp*16)*ROWB + kk*32;
                ldsm4(bf[2*jp][0], bf[2*jp][1], bf[2*jp+1][0], bf[2*jp+1][1], ab);
            }
            #pragma unroll
            for (int i = 0; i < 4; i++){
                const uint32_t aa = st + offA + (uint32_t)(i*16)*ROWB + kk*32;
                uint32_t af[4];
                ldsm4(af[0], af[1], af[2], af[3], aa);
                #pragma unroll
                for (int j = 0; j < 4; j++) mma16816(acc[i][j], af, bf[j]);
            }
        }

        if (kt + 1 < NK) asm volatile("cp.async.wait_group 0;");
        __syncthreads();
    }

    const int r  = lane >> 2;
    const int c4 = lane & 3;

    // Epilogue
    #pragma unroll
    for (int j = 0; j < 4; j++){
        const int col = bc*128 + wn*32 + j*8 + c4*2;
        const float2 bv = *(const float2*)&bias[col];
        if (MODE == 0){
            #pragma unroll
            for (int i = 0; i < 4; i++){
                const int row0 = br*128 + wm*64 + i*16 + r;
                float2 v0 = make_float2(acc[i][j][0] + bv.x, acc[i][j][1] + bv.y);
                float2 v1 = make_float2(acc[i][j][2] + bv.x, acc[i][j][3] + bv.y);
                *(float2*)&Cout[(size_t)row0     * C_ + col] = v0;
                *(float2*)&Cout[(size_t)(row0+8) * C_ + col] = v1;
            }
        } else {
            const int which = col / C_;
            const int rem   = col - which * C_;
            const int hh = rem >> 6;
            const int dd = rem & 63;
            #pragma unroll
            for (int i = 0; i < 4; i++){
                const int row0 = br*128 + wm*64 + i*16 + r;
                const int b0i = row0 >> 10, t0i = row0 & 1023;
                const int row1 = row0 + 8;
                const int b1i = row1 >> 10, t1i = row1 & 1023;
                float v00 = acc[i][j][0] + bv.x, v01 = acc[i][j][1] + bv.y;
                float v10 = acc[i][j][2] + bv.x, v11 = acc[i][j][3] + bv.y;
                if (which == 0){ v00*=0.125f; v01*=0.125f; v10*=0.125f; v11*=0.125f; }
                const size_t o0 = ((size_t)(b0i*H_ + hh)*T_ + t0i)*HS_ + dd;
                const size_t o1 = ((size_t)(b1i*H_ + hh)*T_ + t1i)*HS_ + dd;
                if (which == 0){
                    *(uint32_t*)&g_Qh[o0] = packhf(v00, v01);
                    *(uint32_t*)&g_Ql[o0] = packhf(v00 - hfhi(v00), v01 - hfhi(v01));
                    *(uint32_t*)&g_Qh[o1] = packhf(v10, v11);
                    *(uint32_t*)&g_Ql[o1] = packhf(v10 - hfhi(v10), v11 - hfhi(v11));
                } else if (which == 1){
                    *(uint32_t*)&g_K[o0] = packhf(v00, v01);
                    *(uint32_t*)&g_K[o1] = packhf(v10, v11);
                } else {
                    // V transposed: [B,H,d,T], single fp16
                    const size_t vb0 = ((size_t)(b0i*H_ + hh)*HS_ + dd)*T_;
                    const size_t vb1 = ((size_t)(b1i*H_ + hh)*HS_ + dd)*T_;
                    g_V[vb0      + t0i] = __float2half_rn(v00);
                    g_V[vb0 + T_ + t0i] = __float2half_rn(v01);
                    g_V[vb1      + t1i] = __float2half_rn(v10);
                    g_V[vb1 + T_ + t1i] = __float2half_rn(v11);
                }
            }
        }
    }
}

// ---------------------------------------------------------------------------
// Tensor-core causal flash attention, fp16 2-pass (unchanged from R12):
// S = (Qh+Ql)@K^T (K single); O += (Ph+Pl)@V (V single).
// q-tile 128, k-tiles 64, occ 2, Q fragments register-cached.
// Epilogue now writes SINGLE fp16 Y.
// ---------------------------------------------------------------------------
constexpr int AQ_ROW = 144;
constexpr int AK_ROW = 144;
constexpr int AV_ROW = 144;
constexpr int A_MQ   = 128 * AQ_ROW;     // 18432
constexpr int A_MK   = 64  * AK_ROW;     // 9216
constexpr int A_MV   = 64  * AV_ROW;     // 9216
constexpr int A_QTOT = 2 * A_MQ;         // 36864
constexpr int A_VOFF = A_MK;
constexpr int A_STG  = A_MK + A_MV;      // 18432
constexpr int ATTN_SMEM = A_QTOT + 2*A_STG;  // 73728

__global__ __launch_bounds__(256, 2)
void attn_tc()
{
    extern __shared__ __align__(128) uint8_t smx[];
    const uint32_t sb = smem_u32(smx);

    const int qt  = blockIdx.x;
    const int bh  = blockIdx.y;
    const int tid = threadIdx.x;
    const int lane = tid & 31;
    const int w    = tid >> 5;
    const int r    = lane >> 2;
    const int c4   = lane & 3;

    const size_t qoff = ((size_t)bh*T_ + qt*128) * HS_;
    #pragma unroll
    for (int j = 0; j < 4; j++){
        const int ch = tid + 256*j;
        const int row = ch >> 3, c = ch & 7;
        const uint32_t so = sb + (uint32_t)(row*AQ_ROW + c*16);
        const size_t g = qoff + (size_t)row*HS_ + c*8;
        cpa16(so,        g_Qh + g);
        cpa16(so + A_MQ, g_Ql + g);
    }

    auto load_kv = [&](int kt2, int s){
        const uint32_t st = sb + A_QTOT + (uint32_t)s * A_STG;
        const size_t koff = ((size_t)bh*T_ + kt2*64) * HS_;
        const size_t voff = (size_t)bh*HS_*T_ + kt2*64;
        #pragma unroll
        for (int j = 0; j < 2; j++){
            const int ch = tid + 256*j;
            const int row = ch >> 3, c = ch & 7;
            const uint32_t sk = st + (uint32_t)(row*AK_ROW + c*16);
            cpa16(sk, g_K + koff + (size_t)row*HS_ + c*8);
            const uint32_t sv = st + A_VOFF + (uint32_t)(row*AV_ROW + c*16);
            cpa16(sv, g_V + voff + (size_t)row*T_ + c*8);
        }
        asm volatile("cp.async.commit_group;");
    };

    load_kv(0, 0);

    float m0 = -1e30f, m1 = -1e30f, l0 = 0.f, l1 = 0.f;
    float o[8][4];
    #pragma unroll
    for (int j2 = 0; j2 < 8; j2++)
        #pragma unroll
        for (int q = 0; q < 4; q++) o[j2][q] = 0.f;

    const uint32_t offQ = lm_offA(lane, AQ_ROW) + (uint32_t)(w*16)*AQ_ROW;
    const uint32_t offK = lm_offB(lane, AK_ROW);
    const uint32_t offV = lm_offB(lane, AV_ROW);

    uint32_t qh_r[4][4], ql_r[4][4];

    const int nkt = 2*(qt + 1);

    for (int kt2 = 0; kt2 < nkt; kt2++){
        if (kt2 + 1 < nkt){
            load_kv(kt2 + 1, (kt2 + 1) & 1);
            asm volatile("cp.async.wait_group 1;");
        } else {
            asm volatile("cp.async.wait_group 0;");
        }
        __syncthreads();

        if (kt2 == 0){
            #pragma unroll
            for (int kk = 0; kk < 4; kk++){
                const uint32_t qa = sb + offQ + kk*32;
                ldsm4(qh_r[kk][0], qh_r[kk][1], qh_r[kk][2], qh_r[kk][3], qa);
                ldsm4(ql_r[kk][0], ql_r[kk][1], ql_r[kk][2], ql_r[kk][3],
                      qa + A_MQ);
            }
        }

        const uint32_t st = sb + A_QTOT + (uint32_t)(kt2 & 1) * A_STG;

        float s[8][4];
        #pragma unroll
        for (int j = 0; j < 8; j++){
            s[j][0] = s[j][1] = s[j][2] = s[j][3] = 0.f;
        }
        #pragma unroll
        for (int kk = 0; kk < 4; kk++){
            #pragma unroll
            for (int jq = 0; jq < 2; jq++){
                const uint32_t ka = st + offK
                                  + (uint32_t)(jq*32)*AK_ROW + kk*32;
                uint32_t kh[4][2];
                ldsm4(kh[0][0], kh[0][1], kh[1][0], kh[1][1], ka);
                ldsm4(kh[2][0], kh[2][1], kh[3][0], kh[3][1],
                      ka + (uint32_t)16*AK_ROW);
                float* s0 = s[4*jq + 0]; float* s1 = s[4*jq + 1];
                float* s2 = s[4*jq + 2]; float* s3 = s[4*jq + 3];
                mma16816(s0, qh_r[kk], kh[0]); mma16816(s1, qh_r[kk], kh[1]);
                mma16816(s2, qh_r[kk], kh[2]); mma16816(s3, qh_r[kk], kh[3]);
                mma16816(s0, ql_r[kk], kh[0]); mma16816(s1, ql_r[kk], kh[1]);
                mma16816(s2, ql_r[kk], kh[2]); mma16816(s3, ql_r[kk], kh[3]);
            }
        }

        if (kt2 >= 2*qt){
            const int base = (kt2 - 2*qt)*64;
            const int row0 = w*16 + r;
            #pragma unroll
            for (int j = 0; j < 8; j++){
                const int col0 = base + j*8 + c4*2;
                if (col0     > row0    ) s[j][0] = -1e30f;
                if (col0 + 1 > row0    ) s[j][1] = -1e30f;
                if (col0     > row0 + 8) s[j][2] = -1e30f;
                if (col0 + 1 > row0 + 8) s[j][3] = -1e30f;
            }
        }

        float rm0 = -1e30f, rm1 = -1e30f;
        #pragma unroll
        for (int j = 0; j < 8; j++){
            rm0 = fmaxf(rm0, fmaxf(s[j][0], s[j][1]));
            rm1 = fmaxf(rm1, fmaxf(s[j][2], s[j][3]));
        }
        rm0 = fmaxf(rm0, __shfl_xor_sync(0xffffffffu, rm0, 1));
        rm0 = fmaxf(rm0, __shfl_xor_sync(0xffffffffu, rm0, 2));
        rm1 = fmaxf(rm1, __shfl_xor_sync(0xffffffffu, rm1, 1));
        rm1 = fmaxf(rm1, __shfl_xor_sync(0xffffffffu, rm1, 2));
        const float mn0 = fmaxf(m0, rm0), mn1 = fmaxf(m1, rm1);
        const float a0 = __expf(m0 - mn0), a1 = __expf(m1 - mn1);
        m0 = mn0; m1 = mn1;
        float rs0 = 0.f, rs1 = 0.f;
        #pragma unroll
        for (int j = 0; j < 8; j++){
            s[j][0] = __expf(s[j][0] - mn0);
            s[j][1] = __expf(s[j][1] - mn0);
            s[j][2] = __expf(s[j][2] - mn1);
            s[j][3] = __expf(s[j][3] - mn1);
            rs0 += s[j][0] + s[j][1];
            rs1 += s[j][2] + s[j][3];
        }
        rs0 += __shfl_xor_sync(0xffffffffu, rs0, 1);
        rs0 += __shfl_xor_sync(0xffffffffu, rs0, 2);
        rs1 += __shfl_xor_sync(0xffffffffu, rs1, 1);
        rs1 += __shfl_xor_sync(0xffffffffu, rs1, 2);
        l0 = l0*a0 + rs0;
        l1 = l1*a1 + rs1;
        #pragma unroll
        for (int j2 = 0; j2 < 8; j2++){
            o[j2][0] *= a0; o[j2][1] *= a0;
            o[j2][2] *= a1; o[j2][3] *= a1;
        }

        #pragma unroll
        for (int kk = 0; kk < 4; kk++){
            float ph[8], pl[8];
            #pragma unroll
            for (int e = 0; e < 4; e++){
                ph[e]   = hfhi(s[2*kk  ][e]);  pl[e]   = s[2*kk  ][e] - ph[e];
                ph[4+e] = hfhi(s[2*kk+1][e]);  pl[4+e] = s[2*kk+1][e] - ph[4+e];
            }
            uint32_t a_h[4], a_l[4];
            a_h[0] = packhf(ph[0], ph[1]);  a_h[1] = packhf(ph[2], ph[3]);
            a_h[2] = packhf(ph[4], ph[5]);  a_h[3] = packhf(ph[6], ph[7]);
            a_l[0] = packhf(pl[0], pl[1]);  a_l[1] = packhf(pl[2], pl[3]);
            a_l[2] = packhf(pl[4], pl[5]);  a_l[3] = packhf(pl[6], pl[7]);
            #pragma unroll
            for (int jq = 0; jq < 2; jq++){
                const uint32_t va = st + A_VOFF + offV
                                  + (uint32_t)(jq*32)*AV_ROW + kk*32;
                uint32_t vh[4][2];
                ldsm4(vh[0][0], vh[0][1], vh[1][0], vh[1][1], va);
                ldsm4(vh[2][0], vh[2][1], vh[3][0], vh[3][1],
                      va + (uint32_t)16*AV_ROW);
                float* o0 = o[4*jq + 0]; float* o1 = o[4*jq + 1];
                float* o2 = o[4*jq + 2]; float* o3 = o[4*jq + 3];
                mma16816(o0, a_h, vh[0]); mma16816(o1, a_h, vh[1]);
                mma16816(o2, a_h, vh[2]); mma16816(o3, a_h, vh[3]);
                mma16816(o0, a_l, vh[0]); mma16816(o1, a_l, vh[1]);
                mma16816(o2, a_l, vh[2]); mma16816(o3, a_l, vh[3]);
            }
        }
        __syncthreads();
    }

    // ---- epilogue: write SINGLE fp16 Y [M][768] ----
    const float inv0 = 1.f / l0, inv1 = 1.f / l1;
    const int bq = bh / H_, hh = bh % H_;
    const int t0 = qt*128 + w*16 + r;
    #pragma unroll
    for (int j2 = 0; j2 < 8; j2++){
        const int cc = hh*64 + j2*8 + c4*2;
        const float y0 = o[j2][0]*inv0, y1 = o[j2][1]*inv0;
        const float y2 = o[j2][2]*inv1, y3 = o[j2][3]*inv1;
        const size_t r0 = (size_t)(bq*T_ + t0    )*C_ + cc;
        const size_t r1 = (size_t)(bq*T_ + t0 + 8)*C_ + cc;
        *(uint32_t*)&g_Y[r0] = packhf(y0, y1);
        *(uint32_t*)&g_Y[r1] = packhf(y2, y3);
    }
}

// ---------------------------------------------------------------------------
extern "C" void kernel_launch(void* const* d_in, const int* in_sizes, int n_in,
                              void* d_out, int out_size)
{
    const float* x      = (const float*)d_in[0];
    const float* w_attn = (const float*)d_in[1];
    const float* b_attn = (const float*)d_in[2];
    const float* w_proj = (const float*)d_in[3];
    const float* b_proj = (const float*)d_in[4];
    float* out = (float*)d_out;

    cudaFuncSetAttribute(mma_gemm<1>, cudaFuncAttributeMaxDynamicSharedMemorySize, GEMM_SMEM);
    cudaFuncSetAttribute(mma_gemm<0>, cudaFuncAttributeMaxDynamicSharedMemorySize, GEMM_SMEM);
    cudaFuncSetAttribute(attn_tc, cudaFuncAttributeMaxDynamicSharedMemorySize, ATTN_SMEM);

    convert_x<<<(M_*C_/4 + 255)/256, 256>>>(x);
    transpose_w<0><<<dim3(3*C_/32, C_/32), dim3(32, 8)>>>(w_attn);
    transpose_w<1><<<dim3(C_/32,   C_/32), dim3(32, 8)>>>(w_proj);

    mma_gemm<1><<<dim3(3*C_/128, M_/128), 256, GEMM_SMEM>>>(b_attn, nullptr);
    attn_tc<<<dim3(T_/128, B_*H_), 256, ATTN_SMEM>>>();
    mma_gemm<0><<<dim3(C_/128, M_/128), 256, GEMM_SMEM>>>(b_proj, out);
}

// round 14
// speedup vs baseline: 2.4656x; 1.1849x over previous
#include <cuda_runtime.h>
#include <cuda_fp16.h>
#include <cstdint>

// Problem constants
#define B_  8
#define T_  1024
#define C_  768
#define H_  12
#define HS_ 64
#define M_  8192   // B*T

// ---------------------------------------------------------------------------
// Device-global scratch (no runtime allocation allowed)
// X, Y, weights, Q (prescaled 0.125), K, V(transposed [B,H,hs,T]): single fp16.
// ---------------------------------------------------------------------------
__device__ __half g_X [(size_t)M_*C_];
__device__ __half g_Y [(size_t)M_*C_];
__device__ __half g_Wa[(size_t)3*C_*C_];
__device__ __half g_Wp[(size_t)C_*C_];

__device__ __half g_Q [B_*H_*T_*HS_];
__device__ __half g_K [B_*H_*T_*HS_];
__device__ __half g_V [B_*H_*T_*HS_];

// ---------------------------------------------------------------------------
// Helpers (portable PTX only — compiles for plain sm_103 target)
// ---------------------------------------------------------------------------
__device__ __forceinline__ uint32_t smem_u32(const void* p){
    return (uint32_t)__cvta_generic_to_shared(p);
}
__device__ __forceinline__ void cpa16(uint32_t d, const void* s){
    asm volatile("cp.async.cg.shared.global [%0], [%1], 16;" :: "r"(d), "l"(s));
}
__device__ __forceinline__ void ldsm4(uint32_t& r0, uint32_t& r1,
                                      uint32_t& r2, uint32_t& r3, uint32_t a){
    asm volatile("ldmatrix.sync.aligned.m8n8.x4.shared.b16 {%0,%1,%2,%3}, [%4];"
                 : "=r"(r0), "=r"(r1), "=r"(r2), "=r"(r3) : "r"(a));
}
__device__ __forceinline__ void mma16816(float acc[4], const uint32_t a[4],
                                         const uint32_t b[2]){
    asm volatile(
        "mma.sync.aligned.m16n8k16.row.col.f32.f16.f16.f32 "
        "{%0,%1,%2,%3}, {%4,%5,%6,%7}, {%8,%9}, {%0,%1,%2,%3};"
        : "+f"(acc[0]), "+f"(acc[1]), "+f"(acc[2]), "+f"(acc[3])
        : "r"(a[0]), "r"(a[1]), "r"(a[2]), "r"(a[3]), "r"(b[0]), "r"(b[1]));
}
__device__ __forceinline__ uint32_t packhf(float x, float y){
    __half2 t = __float22half2_rn(make_float2(x, y));
    return *(uint32_t*)&t;
}

// per-lane ldmatrix row-offset helpers (byte offsets within a tile):
__device__ __forceinline__ uint32_t lm_offA(int lane, int rowb){
    return (uint32_t)(((lane & 7) + ((lane >> 3) & 1)*8) * rowb + (lane >> 4)*16);
}
__device__ __forceinline__ uint32_t lm_offB(int lane, int rowb){
    return (uint32_t)(((lane & 7) + (lane >> 4)*8) * rowb + ((lane >> 3) & 1)*16);
}

// ---------------------------------------------------------------------------
// Pre-pass: convert x fp32 -> single fp16
// ---------------------------------------------------------------------------
__global__ void convert_x(const float* __restrict__ src)
{
    const int i = blockIdx.x * blockDim.x + threadIdx.x;   // float4 index
    const int n4 = (M_*C_) / 4;
    if (i >= n4) return;
    const float4 v = ((const float4*)src)[i];
    ((uint32_t*)g_X)[i*2    ] = packhf(v.x, v.y);
    ((uint32_t*)g_X)[i*2 + 1] = packhf(v.z, v.w);
}

// ---------------------------------------------------------------------------
// Pre-pass: transpose weights -> [N][768] single fp16 (K-major)
// ---------------------------------------------------------------------------
template<int WHICH>
__global__ void transpose_w(const float* __restrict__ w)
{
    constexpr int N = (WHICH == 0) ? 3*C_ : C_;
    __half* Hh = (WHICH == 0) ? g_Wa : g_Wp;

    __shared__ float tile[32][33];
    const int nb = blockIdx.x * 32;
    const int kb = blockIdx.y * 32;
    const int tx = threadIdx.x;
    const int ty = threadIdx.y;

    #pragma unroll
    for (int i = ty; i < 32; i += 8)
        tile[i][tx] = w[(size_t)(kb + i) * N + nb + tx];
    __syncthreads();

    #pragma unroll
    for (int i = ty; i < 32; i += 8){
        const float v = tile[tx][i];
        Hh[(size_t)(nb + i) * C_ + kb + tx] = __float2half_rn(v);
    }
}

// ---------------------------------------------------------------------------
// Tensor-core GEMM, pure fp16 1-pass: C = A @ W^T.
// 128x128 CTA tile, 8 warps (2m x 4n), occ 2, ldmatrix loads.
// MODE 1: A=X, B=Wa -> Q(scaled)/K single, V single transposed
// MODE 0: A=Y, B=Wp -> fp32 Cout (d_out)
// ---------------------------------------------------------------------------
constexpr int ROWB   = 80;
constexpr int MATB   = 128 * ROWB;   // 10240
constexpr int STAGEB = 2 * MATB;     // 20480 (A, B)
constexpr int GEMM_SMEM = 2 * STAGEB;// 40960

template<int MODE>
__global__ __launch_bounds__(256, 2)
void mma_gemm(const float* __restrict__ bias, float* __restrict__ Cout)
{
    extern __shared__ __align__(128) uint8_t smem[];

    const __half* Am = (MODE == 1) ? g_X  : g_Y;
    const __half* Bm = (MODE == 1) ? g_Wa : g_Wp;

    const int tid  = threadIdx.x;
    const int lane = tid & 31;
    const int warp = tid >> 5;
    const int wm   = warp & 1;
    const int wn   = warp >> 1;
    const int bc   = blockIdx.x;
    const int br   = blockIdx.y;

    const uint32_t sb = smem_u32(smem);

    auto load_stage = [&](int kt, int s){
        const uint32_t st = sb + (uint32_t)s * STAGEB;
        #pragma unroll
        for (int j = 0; j < 2; j++){
            const int ch  = tid + j*256;
            const int row = ch >> 2;
            const int cc  = ch & 3;
            const uint32_t so = (uint32_t)(row*ROWB + cc*16);
            const size_t ga = (size_t)(br*128 + row) * C_ + kt*32 + cc*8;
            const size_t gb = (size_t)(bc*128 + row) * C_ + kt*32 + cc*8;
            cpa16(st        + so, Am + ga);
            cpa16(st + MATB + so, Bm + gb);
        }
        asm volatile("cp.async.commit_group;");
    };

    float acc[4][4][4];
    #pragma unroll
    for (int i = 0; i < 4; i++)
        #pragma unroll
        for (int j = 0; j < 4; j++)
            #pragma unroll
            for (int q = 0; q < 4; q++) acc[i][j][q] = 0.f;

    constexpr int NK = C_ / 32;    // 24

    load_stage(0, 0);
    asm volatile("cp.async.wait_group 0;");
    __syncthreads();

    const uint32_t offA = lm_offA(lane, ROWB) + (uint32_t)(wm*64)*ROWB;
    const uint32_t offB = lm_offB(lane, ROWB) + (uint32_t)(wn*32)*ROWB + MATB;

    for (int kt = 0; kt < NK; kt++){
        const int cur = kt & 1;
        if (kt + 1 < NK) load_stage(kt + 1, cur ^ 1);

        const uint32_t st = sb + (uint32_t)cur * STAGEB;

        #pragma unroll
        for (int kk = 0; kk < 2; kk++){
            uint32_t bf[4][2];
            #pragma unroll
            for (int jp = 0; jp < 2; jp++){
                const uint32_t ab = st + offB + (uint32_t)(jp*16)*ROWB + kk*32;
                ldsm4(bf[2*jp][0], bf[2*jp][1], bf[2*jp+1][0], bf[2*jp+1][1], ab);
            }
            #pragma unroll
            for (int i = 0; i < 4; i++){
                const uint32_t aa = st + offA + (uint32_t)(i*16)*ROWB + kk*32;
                uint32_t af[4];
                ldsm4(af[0], af[1], af[2], af[3], aa);
                #pragma unroll
                for (int j = 0; j < 4; j++) mma16816(acc[i][j], af, bf[j]);
            }
        }

        if (kt + 1 < NK) asm volatile("cp.async.wait_group 0;");
        __syncthreads();
    }

    const int r  = lane >> 2;
    const int c4 = lane & 3;

    // Epilogue
    #pragma unroll
    for (int j = 0; j < 4; j++){
        const int col = bc*128 + wn*32 + j*8 + c4*2;
        const float2 bv = *(const float2*)&bias[col];
        if (MODE == 0){
            #pragma unroll
            for (int i = 0; i < 4; i++){
                const int row0 = br*128 + wm*64 + i*16 + r;
                float2 v0 = make_float2(acc[i][j][0] + bv.x, acc[i][j][1] + bv.y);
                float2 v1 = make_float2(acc[i][j][2] + bv.x, acc[i][j][3] + bv.y);
                *(float2*)&Cout[(size_t)row0     * C_ + col] = v0;
                *(float2*)&Cout[(size_t)(row0+8) * C_ + col] = v1;
            }
        } else {
            const int which = col / C_;
            const int rem   = col - which * C_;
            const int hh = rem >> 6;
            const int dd = rem & 63;
            #pragma unroll
            for (int i = 0; i < 4; i++){
                const int row0 = br*128 + wm*64 + i*16 + r;
                const int b0i = row0 >> 10, t0i = row0 & 1023;
                const int row1 = row0 + 8;
                const int b1i = row1 >> 10, t1i = row1 & 1023;
                float v00 = acc[i][j][0] + bv.x, v01 = acc[i][j][1] + bv.y;
                float v10 = acc[i][j][2] + bv.x, v11 = acc[i][j][3] + bv.y;
                if (which == 0){ v00*=0.125f; v01*=0.125f; v10*=0.125f; v11*=0.125f; }
                const size_t o0 = ((size_t)(b0i*H_ + hh)*T_ + t0i)*HS_ + dd;
                const size_t o1 = ((size_t)(b1i*H_ + hh)*T_ + t1i)*HS_ + dd;
                if (which == 0){
                    *(uint32_t*)&g_Q[o0] = packhf(v00, v01);
                    *(uint32_t*)&g_Q[o1] = packhf(v10, v11);
                } else if (which == 1){
                    *(uint32_t*)&g_K[o0] = packhf(v00, v01);
                    *(uint32_t*)&g_K[o1] = packhf(v10, v11);
                } else {
                    // V transposed: [B,H,d,T]
                    const size_t vb0 = ((size_t)(b0i*H_ + hh)*HS_ + dd)*T_;
                    const size_t vb1 = ((size_t)(b1i*H_ + hh)*HS_ + dd)*T_;
                    g_V[vb0      + t0i] = __float2half_rn(v00);
                    g_V[vb0 + T_ + t0i] = __float2half_rn(v01);
                    g_V[vb1      + t1i] = __float2half_rn(v10);
                    g_V[vb1 + T_ + t1i] = __float2half_rn(v11);
                }
            }
        }
    }
}

// ---------------------------------------------------------------------------
// Tensor-core causal flash attention, pure fp16 (1-pass S, 1-pass PV).
// q-tile 128, k-tiles 64, occ 2, Q fragments register-cached (16 regs).
// smem: Q 18432 + 2 stages x (K 9216 + V 9216) = 55296 B.
// ---------------------------------------------------------------------------
constexpr int AQ_ROW = 144;
constexpr int AK_ROW = 144;
constexpr int AV_ROW = 144;
constexpr int A_MQ   = 128 * AQ_ROW;     // 18432
constexpr int A_MK   = 64  * AK_ROW;     // 9216
constexpr int A_MV   = 64  * AV_ROW;     // 9216
constexpr int A_VOFF = A_MK;
constexpr int A_STG  = A_MK + A_MV;      // 18432
constexpr int ATTN_SMEM = A_MQ + 2*A_STG;  // 55296

__global__ __launch_bounds__(256, 2)
void attn_tc()
{
    extern __shared__ __align__(128) uint8_t smx[];
    const uint32_t sb = smem_u32(smx);

    const int qt  = blockIdx.x;
    const int bh  = blockIdx.y;
    const int tid = threadIdx.x;
    const int lane = tid & 31;
    const int w    = tid >> 5;
    const int r    = lane >> 2;
    const int c4   = lane & 3;

    const size_t qoff = ((size_t)bh*T_ + qt*128) * HS_;
    #pragma unroll
    for (int j = 0; j < 4; j++){
        const int ch = tid + 256*j;
        const int row = ch >> 3, c = ch & 7;
        cpa16(sb + (uint32_t)(row*AQ_ROW + c*16),
              g_Q + qoff + (size_t)row*HS_ + c*8);
    }

    auto load_kv = [&](int kt2, int s){
        const uint32_t st = sb + A_MQ + (uint32_t)s * A_STG;
        const size_t koff = ((size_t)bh*T_ + kt2*64) * HS_;
        const size_t voff = (size_t)bh*HS_*T_ + kt2*64;
        #pragma unroll
        for (int j = 0; j < 2; j++){
            const int ch = tid + 256*j;
            const int row = ch >> 3, c = ch & 7;
            cpa16(st + (uint32_t)(row*AK_ROW + c*16),
                  g_K + koff + (size_t)row*HS_ + c*8);
            cpa16(st + A_VOFF + (uint32_t)(row*AV_ROW + c*16),
                  g_V + voff + (size_t)row*T_ + c*8);
        }
        asm volatile("cp.async.commit_group;");
    };

    load_kv(0, 0);

    float m0 = -1e30f, m1 = -1e30f, l0 = 0.f, l1 = 0.f;
    float o[8][4];
    #pragma unroll
    for (int j2 = 0; j2 < 8; j2++)
        #pragma unroll
        for (int q = 0; q < 4; q++) o[j2][q] = 0.f;

    const uint32_t offQ = lm_offA(lane, AQ_ROW) + (uint32_t)(w*16)*AQ_ROW;
    const uint32_t offK = lm_offB(lane, AK_ROW);
    const uint32_t offV = lm_offB(lane, AV_ROW);

    uint32_t q_r[4][4];   // loop-invariant Q fragments

    const int nkt = 2*(qt + 1);

    for (int kt2 = 0; kt2 < nkt; kt2++){
        if (kt2 + 1 < nkt){
            load_kv(kt2 + 1, (kt2 + 1) & 1);
            asm volatile("cp.async.wait_group 1;");
        } else {
            asm volatile("cp.async.wait_group 0;");
        }
        __syncthreads();

        if (kt2 == 0){
            #pragma unroll
            for (int kk = 0; kk < 4; kk++){
                const uint32_t qa = sb + offQ + kk*32;
                ldsm4(q_r[kk][0], q_r[kk][1], q_r[kk][2], q_r[kk][3], qa);
            }
        }

        const uint32_t st = sb + A_MQ + (uint32_t)(kt2 & 1) * A_STG;

        // ---- S = Q @ K^T (1-pass), 64 k-rows ----
        float s[8][4];
        #pragma unroll
        for (int j = 0; j < 8; j++){
            s[j][0] = s[j][1] = s[j][2] = s[j][3] = 0.f;
        }
        #pragma unroll
        for (int kk = 0; kk < 4; kk++){
            #pragma unroll
            for (int jq = 0; jq < 2; jq++){
                const uint32_t ka = st + offK
                                  + (uint32_t)(jq*32)*AK_ROW + kk*32;
                uint32_t kh[4][2];
                ldsm4(kh[0][0], kh[0][1], kh[1][0], kh[1][1], ka);
                ldsm4(kh[2][0], kh[2][1], kh[3][0], kh[3][1],
                      ka + (uint32_t)16*AK_ROW);
                mma16816(s[4*jq + 0], q_r[kk], kh[0]);
                mma16816(s[4*jq + 1], q_r[kk], kh[1]);
                mma16816(s[4*jq + 2], q_r[kk], kh[2]);
                mma16816(s[4*jq + 3], q_r[kk], kh[3]);
            }
        }

        // ---- causal mask ----
        if (kt2 >= 2*qt){
            const int base = (kt2 - 2*qt)*64;
            const int row0 = w*16 + r;
            #pragma unroll
            for (int j = 0; j < 8; j++){
                const int col0 = base + j*8 + c4*2;
                if (col0     > row0    ) s[j][0] = -1e30f;
                if (col0 + 1 > row0    ) s[j][1] = -1e30f;
                if (col0     > row0 + 8) s[j][2] = -1e30f;
                if (col0 + 1 > row0 + 8) s[j][3] = -1e30f;
            }
        }

        // ---- online softmax ----
        float rm0 = -1e30f, rm1 = -1e30f;
        #pragma unroll
        for (int j = 0; j < 8; j++){
            rm0 = fmaxf(rm0, fmaxf(s[j][0], s[j][1]));
            rm1 = fmaxf(rm1, fmaxf(s[j][2], s[j][3]));
        }
        rm0 = fmaxf(rm0, __shfl_xor_sync(0xffffffffu, rm0, 1));
        rm0 = fmaxf(rm0, __shfl_xor_sync(0xffffffffu, rm0, 2));
        rm1 = fmaxf(rm1, __shfl_xor_sync(0xffffffffu, rm1, 1));
        rm1 = fmaxf(rm1, __shfl_xor_sync(0xffffffffu, rm1, 2));
        const float mn0 = fmaxf(m0, rm0), mn1 = fmaxf(m1, rm1);
        const float a0 = __expf(m0 - mn0), a1 = __expf(m1 - mn1);
        m0 = mn0; m1 = mn1;
        float rs0 = 0.f, rs1 = 0.f;
        #pragma unroll
        for (int j = 0; j < 8; j++){
            s[j][0] = __expf(s[j][0] - mn0);
            s[j][1] = __expf(s[j][1] - mn0);
            s[j][2] = __expf(s[j][2] - mn1);
            s[j][3] = __expf(s[j][3] - mn1);
            rs0 += s[j][0] + s[j][1];
            rs1 += s[j][2] + s[j][3];
        }
        rs0 += __shfl_xor_sync(0xffffffffu, rs0, 1);
        rs0 += __shfl_xor_sync(0xffffffffu, rs0, 2);
        rs1 += __shfl_xor_sync(0xffffffffu, rs1, 1);
        rs1 += __shfl_xor_sync(0xffffffffu, rs1, 2);
        l0 = l0*a0 + rs0;
        l1 = l1*a1 + rs1;
        #pragma unroll
        for (int j2 = 0; j2 < 8; j2++){
            o[j2][0] *= a0; o[j2][1] *= a0;
            o[j2][2] *= a1; o[j2][3] *= a1;
        }

        // ---- O += P @ V (1-pass, P single fp16) ----
        #pragma unroll
        for (int kk = 0; kk < 4; kk++){
            uint32_t a_h[4];
            a_h[0] = packhf(s[2*kk  ][0], s[2*kk  ][1]);
            a_h[1] = packhf(s[2*kk  ][2], s[2*kk  ][3]);
            a_h[2] = packhf(s[2*kk+1][0], s[2*kk+1][1]);
            a_h[3] = packhf(s[2*kk+1][2], s[2*kk+1][3]);
            #pragma unroll
            for (int jq = 0; jq < 2; jq++){
                const uint32_t va = st + A_VOFF + offV
                                  + (uint32_t)(jq*32)*AV_ROW + kk*32;
                uint32_t vh[4][2];
                ldsm4(vh[0][0], vh[0][1], vh[1][0], vh[1][1], va);
                ldsm4(vh[2][0], vh[2][1], vh[3][0], vh[3][1],
                      va + (uint32_t)16*AV_ROW);
                mma16816(o[4*jq + 0], a_h, vh[0]);
                mma16816(o[4*jq + 1], a_h, vh[1]);
                mma16816(o[4*jq + 2], a_h, vh[2]);
                mma16816(o[4*jq + 3], a_h, vh[3]);
            }
        }
        __syncthreads();
    }

    // ---- epilogue: write single fp16 Y [M][768] ----
    const float inv0 = 1.f / l0, inv1 = 1.f / l1;
    const int bq = bh / H_, hh = bh % H_;
    const int t0 = qt*128 + w*16 + r;
    #pragma unroll
    for (int j2 = 0; j2 < 8; j2++){
        const int cc = hh*64 + j2*8 + c4*2;
        const size_t r0 = (size_t)(bq*T_ + t0    )*C_ + cc;
        const size_t r1 = (size_t)(bq*T_ + t0 + 8)*C_ + cc;
        *(uint32_t*)&g_Y[r0] = packhf(o[j2][0]*inv0, o[j2][1]*inv0);
        *(uint32_t*)&g_Y[r1] = packhf(o[j2][2]*inv1, o[j2][3]*inv1);
    }
}

// ---------------------------------------------------------------------------
extern "C" void kernel_launch(void* const* d_in, const int* in_sizes, int n_in,
                              void* d_out, int out_size)
{
    const float* x      = (const float*)d_in[0];
    const float* w_attn = (const float*)d_in[1];
    const float* b_attn = (const float*)d_in[2];
    const float* w_proj = (const float*)d_in[3];
    const float* b_proj = (const float*)d_in[4];
    float* out = (float*)d_out;

    cudaFuncSetAttribute(mma_gemm<1>, cudaFuncAttributeMaxDynamicSharedMemorySize, GEMM_SMEM);
    cudaFuncSetAttribute(mma_gemm<0>, cudaFuncAttributeMaxDynamicSharedMemorySize, GEMM_SMEM);
    cudaFuncSetAttribute(attn_tc, cudaFuncAttributeMaxDynamicSharedMemorySize, ATTN_SMEM);

    convert_x<<<(M_*C_/4 + 255)/256, 256>>>(x);
    transpose_w<0><<<dim3(3*C_/32, C_/32), dim3(32, 8)>>>(w_attn);
    transpose_w<1><<<dim3(C_/32,   C_/32), dim3(32, 8)>>>(w_proj);

    mma_gemm<1><<<dim3(3*C_/128, M_/128), 256, GEMM_SMEM>>>(b_attn, nullptr);
    attn_tc<<<dim3(T_/128, B_*H_), 256, ATTN_SMEM>>>();
    mma_gemm<0><<<dim3(C_/128, M_/128), 256, GEMM_SMEM>>>(b_proj, out);
}